// round 9
// baseline (speedup 1.0000x reference)
#include <cuda_runtime.h>
#include <cuda_bf16.h>
#include <cuda_fp16.h>
#include <cstdint>

#define H   128
#define NUc 200000
#define NMc 80000
#define FDc 512
#define Ec  2000000

// ---------------- scratch (device globals; no cudaMalloc allowed) ------------
__device__ __nv_bfloat16 g_mxh[NMc * H];   // movie_x hi plane
__device__ __nv_bfloat16 g_mxl[NMc * H];   // movie_x lo plane
__device__ __nv_bfloat16 g_mhh[NMc * H];   // movie_h hi
__device__ __nv_bfloat16 g_mhl[NMc * H];   // movie_h lo
__device__ __nv_bfloat16 g_mah[NMc * H];   // macc-mean hi
__device__ __nv_bfloat16 g_mal[NMc * H];   // macc-mean lo
__device__ float  g_movie_o[NMc * H];      // conv2 movie output (fp32)
__device__ __half g_movie_y[NMc * H];      // conv1 movie_y (fp16)
__device__ __half g_movie_z[NMc * H];      // conv2 movie_z (fp16)
__device__ __half g_userH[NUc * H];        // user_h (fp16)
__device__ float  g_userB[NUc * H];        // uacc-mean -> user_o (fp32)
__device__ int    g_ucnt[NUc];
__device__ int    g_mcnt[NMc];
__device__ int    g_uoffs[NUc + 1];
__device__ int    g_moffs[NMc + 1];
__device__ int    g_ucur[NUc];
__device__ int    g_mcur[NMc];
__device__ int    g_uadj[Ec];
__device__ int    g_madj[Ec];
__device__ int    g_ubsum[256];
__device__ int    g_mbsum[256];
__device__ float  g_cA[H];
__device__ float  g_d1[H];

// pre-split transposed weights: [0,65536)=Wm(K=512); then 6 H x H mats
#define WTOT (65536 + 6 * 16384)
__device__ __nv_bfloat16 g_Wth[WTOT];
__device__ __nv_bfloat16 g_Wtl[WTOT];

// ---------------- split helpers ----------------------------------------------
// cheap split of a pair: hi = truncated bf16 (top 16 bits), lo = rn(x - hi)
__device__ __forceinline__ void split_pair(float x0, float x1, uint32_t& hi01, uint32_t& lo01) {
    uint32_t xi = __float_as_uint(x0), yi = __float_as_uint(x1);
    hi01 = __byte_perm(xi, yi, 0x7632);
    float rx = x0 - __uint_as_float(xi & 0xFFFF0000u);
    float ry = x1 - __uint_as_float(yi & 0xFFFF0000u);
    asm("cvt.rn.bf16x2.f32 %0, %1, %2;" : "=r"(lo01) : "f"(ry), "f"(rx));
}
__device__ __forceinline__ void split2(float x, unsigned short& hi, unsigned short& lo) {
    __nv_bfloat16 h = __float2bfloat16(x);
    float hf = __bfloat162float(h);
    __nv_bfloat16 l = __float2bfloat16(x - hf);
    hi = __bfloat16_as_ushort(h);
    lo = __bfloat16_as_ushort(l);
}
__device__ __forceinline__ void mma16816(float* d, const uint32_t* a, uint32_t b0, uint32_t b1) {
    asm volatile("mma.sync.aligned.m16n8k16.row.col.f32.bf16.bf16.f32 "
                 "{%0,%1,%2,%3}, {%4,%5,%6,%7}, {%8,%9}, {%0,%1,%2,%3};\n"
                 : "+f"(d[0]), "+f"(d[1]), "+f"(d[2]), "+f"(d[3])
                 : "r"(a[0]), "r"(a[1]), "r"(a[2]), "r"(a[3]), "r"(b0), "r"(b1));
}

// ---------------- small kernels ----------------------------------------------
__global__ void zero_kernel(float* __restrict__ p, int n4) {
    int i = blockIdx.x * blockDim.x + threadIdx.x;
    if (i < n4) ((float4*)p)[i] = make_float4(0.f, 0.f, 0.f, 0.f);
}
__global__ void prep_weights(const float* __restrict__ Wm,
                             const float* __restrict__ M0, const float* __restrict__ M1,
                             const float* __restrict__ M2, const float* __restrict__ M3,
                             const float* __restrict__ M4, const float* __restrict__ M5) {
    int idx = blockIdx.x * blockDim.x + threadIdx.x;
    if (idx >= WTOT) return;
    const float* src; int K, off;
    if (idx < 65536) { src = Wm; K = 512; off = idx; }
    else {
        int r = idx - 65536;
        int m = r >> 14; off = r & 16383; K = 128;
        src = (m == 0) ? M0 : (m == 1) ? M1 : (m == 2) ? M2 : (m == 3) ? M3 : (m == 4) ? M4 : M5;
    }
    int n = off / K, k = off - n * K;
    float v = src[(size_t)k * H + n];
    unsigned short h, l;
    split2(v, h, l);
    ((unsigned short*)g_Wth)[idx] = h;
    ((unsigned short*)g_Wtl)[idx] = l;
}
__global__ void count_kernel(const int* __restrict__ src, const int* __restrict__ dst, int E) {
    int e = blockIdx.x * blockDim.x + threadIdx.x;
    if (e < E) {
        atomicAdd(&g_ucnt[src[e]], 1);
        atomicAdd(&g_mcnt[dst[e]], 1);
    }
}
__global__ void scan1_kernel(const int* __restrict__ in, int* __restrict__ out,
                             int* __restrict__ bsums, int n) {
    __shared__ int s[1024];
    int i = blockIdx.x * 1024 + threadIdx.x;
    int x = (i < n) ? in[i] : 0;
    s[threadIdx.x] = x;
    __syncthreads();
    #pragma unroll
    for (int d = 1; d < 1024; d <<= 1) {
        int t = (threadIdx.x >= d) ? s[threadIdx.x - d] : 0;
        __syncthreads();
        s[threadIdx.x] += t;
        __syncthreads();
    }
    if (i < n) out[i] = s[threadIdx.x] - x;
    if (threadIdx.x == 1023) bsums[blockIdx.x] = s[1023];
}
__global__ void scan2_kernel(int* __restrict__ bsums, int nb, int* __restrict__ offs, int n) {
    if (threadIdx.x == 0 && blockIdx.x == 0) {
        int run = 0;
        for (int i = 0; i < nb; i++) { int v = bsums[i]; bsums[i] = run; run += v; }
        offs[n] = run;
    }
}
__global__ void scan3_kernel(int* __restrict__ offs, const int* __restrict__ bsums,
                             int* __restrict__ cur, int n) {
    int i = blockIdx.x * blockDim.x + threadIdx.x;
    if (i < n) {
        int v = offs[i] + bsums[i >> 10];
        offs[i] = v;
        cur[i] = v;
    }
}
__global__ void fill_kernel(const int* __restrict__ src, const int* __restrict__ dst, int E) {
    int e = blockIdx.x * blockDim.x + threadIdx.x;
    if (e >= E) return;
    int u = src[e], m = dst[e];
    int pu = atomicAdd(&g_ucur[u], 1);
    g_uadj[pu] = m;
    int pm = atomicAdd(&g_mcur[m], 1);
    g_madj[pm] = u;
}
__global__ void vec_kernel(const float* __restrict__ u0, const float* __restrict__ Wl1um,
                           const float* __restrict__ bl1mu, const float* __restrict__ Wr1mu) {
    int j = threadIdx.x;
    float a = 0.f, b = 0.f;
    for (int k = 0; k < H; k++) {
        float u = u0[k];
        a += u * Wl1um[k * H + j];
        b += u * Wr1mu[k * H + j];
    }
    g_cA[j] = a;
    g_d1[j] = b + bl1mu[j];
}

// warp-per-node CSR gather over fp16 rows: 16 lanes x 16B, 2 rows/iter.
// OUTK: 0=f32, 1=f16, 2=bf16 hi/lo planes. FUSED1: mean+d1+relu. MEAN: mean only.
template<int OUTK, bool FUSED1, bool MEAN>
__global__ void gather_kernel(const __half* __restrict__ rows, const int* __restrict__ adj,
                              const int* __restrict__ offs, void* __restrict__ out,
                              void* __restrict__ outl, const float* __restrict__ d1, int N)
{
    int node = (blockIdx.x * blockDim.x + threadIdx.x) >> 5;
    int lane = threadIdx.x & 31;
    if (node >= N) return;
    int beg = offs[node], end = offs[node + 1];
    int hsel = lane >> 4;
    int sub  = lane & 15;
    float acc[8];
    #pragma unroll
    for (int j = 0; j < 8; j++) acc[j] = 0.f;

    for (int base = beg; base < end; base += 32) {
        int nn = min(32, end - base);
        int myidx = (lane < nn) ? __ldg(&adj[base + lane]) : 0;
        int np = (nn + 1) >> 1;
        #pragma unroll 4
        for (int t = 0; t < np; t++) {
            int sel = 2 * t + hsel;
            int ii = __shfl_sync(0xffffffffu, myidx, sel & 31);
            if (sel < nn) {
                uint4 v = *(const uint4*)&rows[(size_t)ii * H + sub * 8];
                float2 f0 = __half22float2(*(__half2*)&v.x);
                float2 f1 = __half22float2(*(__half2*)&v.y);
                float2 f2 = __half22float2(*(__half2*)&v.z);
                float2 f3 = __half22float2(*(__half2*)&v.w);
                acc[0] += f0.x; acc[1] += f0.y; acc[2] += f1.x; acc[3] += f1.y;
                acc[4] += f2.x; acc[5] += f2.y; acc[6] += f3.x; acc[7] += f3.y;
            }
        }
    }
    #pragma unroll
    for (int j = 0; j < 8; j++) acc[j] += __shfl_xor_sync(0xffffffffu, acc[j], 16);

    if (lane < 16) {
        if (FUSED1) {
            float rinv = 1.f / fmaxf((float)(end - beg), 1.f);
            float4 d0 = *(const float4*)&d1[sub * 8];
            float4 d4 = *(const float4*)&d1[sub * 8 + 4];
            acc[0] = fmaxf(acc[0] * rinv + d0.x, 0.f);
            acc[1] = fmaxf(acc[1] * rinv + d0.y, 0.f);
            acc[2] = fmaxf(acc[2] * rinv + d0.z, 0.f);
            acc[3] = fmaxf(acc[3] * rinv + d0.w, 0.f);
            acc[4] = fmaxf(acc[4] * rinv + d4.x, 0.f);
            acc[5] = fmaxf(acc[5] * rinv + d4.y, 0.f);
            acc[6] = fmaxf(acc[6] * rinv + d4.z, 0.f);
            acc[7] = fmaxf(acc[7] * rinv + d4.w, 0.f);
        } else if (MEAN) {
            float rinv = 1.f / fmaxf((float)(end - beg), 1.f);
            #pragma unroll
            for (int j = 0; j < 8; j++) acc[j] *= rinv;
        }
        size_t off = (size_t)node * H + sub * 8;
        if (OUTK == 1) {
            uint4 pk;
            *(__half2*)&pk.x = __floats2half2_rn(acc[0], acc[1]);
            *(__half2*)&pk.y = __floats2half2_rn(acc[2], acc[3]);
            *(__half2*)&pk.z = __floats2half2_rn(acc[4], acc[5]);
            *(__half2*)&pk.w = __floats2half2_rn(acc[6], acc[7]);
            *(uint4*)&((__half*)out)[off] = pk;
        } else if (OUTK == 2) {
            uint4 ph, pl;
            split_pair(acc[0], acc[1], ph.x, pl.x);
            split_pair(acc[2], acc[3], ph.y, pl.y);
            split_pair(acc[4], acc[5], ph.z, pl.z);
            split_pair(acc[6], acc[7], ph.w, pl.w);
            *(uint4*)&((__nv_bfloat16*)out)[off]  = ph;
            *(uint4*)&((__nv_bfloat16*)outl)[off] = pl;
        } else {
            float* o = &((float*)out)[off];
            *(float4*)o       = make_float4(acc[0], acc[1], acc[2], acc[3]);
            *(float4*)(o + 4) = make_float4(acc[4], acc[5], acc[6], acc[7]);
        }
    }
}

__global__ void dot_kernel(const int* __restrict__ lu, const int* __restrict__ lm,
                           const float* __restrict__ uo, const float* __restrict__ mo,
                           float* __restrict__ out, int EL) {
    int gw = (blockIdx.x * blockDim.x + threadIdx.x) >> 5;
    int lane = threadIdx.x & 31;
    if (gw >= EL) return;
    int u = __ldg(&lu[gw]);
    int m = __ldg(&lm[gw]);
    float4 a = *(const float4*)&uo[(size_t)u * H + lane * 4];
    float4 b = *(const float4*)&mo[(size_t)m * H + lane * 4];
    float s = a.x * b.x + a.y * b.y + a.z * b.z + a.w * b.w;
    #pragma unroll
    for (int o = 16; o; o >>= 1) s += __shfl_xor_sync(0xffffffffu, s, o);
    if (lane == 0) out[gw] = s;
}

// ---------------- GEMM common -------------------------------------------------
#define SROW 72
#define SROWF 136
#define GSMEM (4 * 128 * SROW * 2 + 512)
#define GSMEM_D2B (2 * 128 * SROWF * 2 + 2 * 128 * SROW * 2 + 512)

// pure-copy B chunk (pre-split, transposed): uint4 per plane
__device__ __forceinline__ void load_B_pre(const __nv_bfloat16* __restrict__ Wth,
                                           const __nv_bfloat16* __restrict__ Wtl,
                                           int K, int kbase,
                                           __nv_bfloat16* sBh, __nv_bfloat16* sBl, int tid) {
    #pragma unroll
    for (int t = 0; t < 4; t++) {
        int idx = tid + t * 256;
        int n = idx >> 3, kq = idx & 7;
        size_t go = (size_t)n * K + kbase + kq * 8;
        uint4 h = *(const uint4*)&Wth[go];
        uint4 l = *(const uint4*)&Wtl[go];
        int o = n * SROW + kq * 8;
        *(uint4*)&sBh[o] = h;
        *(uint4*)&sBl[o] = l;
    }
}
// pure-copy A chunk from planes (row-major [M,KTOT] bf16 planes)
__device__ __forceinline__ void load_A_planes(const __nv_bfloat16* __restrict__ Ah,
                                              const __nv_bfloat16* __restrict__ Al,
                                              int KTOT, int kbase, int row0, int M,
                                              __nv_bfloat16* sAh, __nv_bfloat16* sAl, int tid) {
    #pragma unroll
    for (int t = 0; t < 4; t++) {
        int idx = tid + t * 256;
        int r = idx >> 3, q = idx & 7;
        int rg = row0 + r;
        uint4 h = make_uint4(0, 0, 0, 0), l = make_uint4(0, 0, 0, 0);
        if (rg < M) {
            size_t go = (size_t)rg * KTOT + kbase + q * 8;
            h = *(const uint4*)&Ah[go];
            l = *(const uint4*)&Al[go];
        }
        int o = r * SROW + q * 8;
        *(uint4*)&sAh[o] = h;
        *(uint4*)&sAl[o] = l;
    }
}

template<int AST>
__device__ __forceinline__ void compute_chunk(const __nv_bfloat16* sAh, const __nv_bfloat16* sAl,
                                              const __nv_bfloat16* sBh, const __nv_bfloat16* sBl,
                                              int akof, int wm, int wn, int g, int tig,
                                              float acc[2][8][4]) {
    #pragma unroll
    for (int ks = 0; ks < 4; ks++) {
        int kof = ks * 16 + tig * 2;
        uint32_t ah[2][4], al[2][4];
        #pragma unroll
        for (int i = 0; i < 2; i++) {
            int r0 = (wm * 32 + i * 16 + g) * AST + akof + kof;
            int r1 = r0 + 8 * AST;
            ah[i][0] = *(const uint32_t*)&sAh[r0];
            ah[i][1] = *(const uint32_t*)&sAh[r1];
            ah[i][2] = *(const uint32_t*)&sAh[r0 + 8];
            ah[i][3] = *(const uint32_t*)&sAh[r1 + 8];
            al[i][0] = *(const uint32_t*)&sAl[r0];
            al[i][1] = *(const uint32_t*)&sAl[r1];
            al[i][2] = *(const uint32_t*)&sAl[r0 + 8];
            al[i][3] = *(const uint32_t*)&sAl[r1 + 8];
        }
        #pragma unroll
        for (int j = 0; j < 8; j++) {
            int nb = (wn * 64 + j * 8 + g) * SROW + kof;
            uint32_t bh0 = *(const uint32_t*)&sBh[nb];
            uint32_t bh1 = *(const uint32_t*)&sBh[nb + 8];
            uint32_t bl0 = *(const uint32_t*)&sBl[nb];
            uint32_t bl1 = *(const uint32_t*)&sBl[nb + 8];
            mma16816(acc[0][j], ah[0], bh0, bh1);
            mma16816(acc[1][j], ah[1], bh0, bh1);
            mma16816(acc[0][j], ah[0], bl0, bl1);
            mma16816(acc[1][j], ah[1], bl0, bl1);
            mma16816(acc[0][j], al[0], bh0, bh1);
            mma16816(acc[1][j], al[1], bh0, bh1);
        }
    }
}

// ---------------- generic GEMM ------------------------------------------------
// AK: 0=f32 (cheap split), 1=f16 (cheap split), 2=planes (copy)
// CK: 0=f32, 1=f16, 2=planes
template<int KTOT, int AK, int CK, bool BIAS, bool ADDM>
__global__ void __launch_bounds__(256)
gemm_mma(const void* __restrict__ Av, const void* __restrict__ Avl,
         const __nv_bfloat16* __restrict__ Wth, const __nv_bfloat16* __restrict__ Wtl,
         const float* __restrict__ bias, const float* __restrict__ addmat,
         void* __restrict__ Cv, void* __restrict__ Cvl, int M)
{
    extern __shared__ char smem[];
    __nv_bfloat16* sAh = (__nv_bfloat16*)smem;
    __nv_bfloat16* sAl = sAh + 128 * SROW;
    __nv_bfloat16* sBh = sAl + 128 * SROW;
    __nv_bfloat16* sBl = sBh + 128 * SROW;

    const int tid = threadIdx.x;
    const int wid = tid >> 5, lid = tid & 31;
    const int wm = wid >> 1, wn = wid & 1;
    const int g = lid >> 2, tig = lid & 3;
    const int row0 = blockIdx.x * 128;

    float acc[2][8][4];
    #pragma unroll
    for (int i = 0; i < 2; i++)
        #pragma unroll
        for (int j = 0; j < 8; j++)
            #pragma unroll
            for (int q = 0; q < 4; q++) acc[i][j][q] = 0.f;

    const int NCH = KTOT / 64;
    for (int c = 0; c < NCH; c++) {
        if (c > 0) __syncthreads();
        if (AK == 2) {
            load_A_planes((const __nv_bfloat16*)Av, (const __nv_bfloat16*)Avl,
                          KTOT, c * 64, row0, M, sAh, sAl, tid);
        } else {
            #pragma unroll
            for (int t = 0; t < 8; t++) {
                int idx = tid + t * 256;
                int r = idx >> 4, q = idx & 15;
                int rg = row0 + r;
                float4 v = make_float4(0.f, 0.f, 0.f, 0.f);
                if (rg < M) {
                    if (AK == 1) {
                        const __half* A = (const __half*)Av;
                        uint2 hv = *(const uint2*)&A[(size_t)rg * KTOT + c * 64 + q * 4];
                        float2 f0 = __half22float2(*(__half2*)&hv.x);
                        float2 f1 = __half22float2(*(__half2*)&hv.y);
                        v = make_float4(f0.x, f0.y, f1.x, f1.y);
                    } else {
                        v = *(const float4*)&((const float*)Av)[(size_t)rg * KTOT + c * 64 + q * 4];
                    }
                }
                uint2 hp, lp;
                split_pair(v.x, v.y, hp.x, lp.x);
                split_pair(v.z, v.w, hp.y, lp.y);
                int o = r * SROW + q * 4;
                *(uint2*)&sAh[o] = hp;
                *(uint2*)&sAl[o] = lp;
            }
        }
        load_B_pre(Wth, Wtl, KTOT, c * 64, sBh, sBl, tid);
        __syncthreads();
        compute_chunk<SROW>(sAh, sAl, sBh, sBl, 0, wm, wn, g, tig, acc);
    }

    #pragma unroll
    for (int i = 0; i < 2; i++) {
        #pragma unroll
        for (int hf = 0; hf < 2; hf++) {
            int r = row0 + wm * 32 + i * 16 + g + hf * 8;
            if (r >= M) continue;
            #pragma unroll
            for (int j = 0; j < 8; j++) {
                int col = wn * 64 + j * 8 + tig * 2;
                float x0 = acc[i][j][hf * 2 + 0];
                float x1 = acc[i][j][hf * 2 + 1];
                if (BIAS) { x0 += bias[col]; x1 += bias[col + 1]; }
                if (ADDM) {
                    float2 m = *(const float2*)&addmat[(size_t)r * H + col];
                    x0 += m.x; x1 += m.y;
                }
                size_t off = (size_t)r * H + col;
                if (CK == 1) {
                    *(__half2*)&((__half*)Cv)[off] = __floats2half2_rn(x0, x1);
                } else if (CK == 2) {
                    uint32_t hh, ll;
                    split_pair(x0, x1, hh, ll);
                    *(uint32_t*)&((__nv_bfloat16*)Cv)[off]  = hh;
                    *(uint32_t*)&((__nv_bfloat16*)Cvl)[off] = ll;
                } else {
                    *(float2*)&((float*)Cv)[off] = make_float2(x0, x1);
                }
            }
        }
    }
}

// ---------------- conv1 movie dual-B (A = movie_x planes) ---------------------
__global__ void __launch_bounds__(256)
gemm_conv1_movie(const __nv_bfloat16* __restrict__ Ah, const __nv_bfloat16* __restrict__ Al,
                 const __nv_bfloat16* __restrict__ W0h, const __nv_bfloat16* __restrict__ W0l,
                 const __nv_bfloat16* __restrict__ W1h, const __nv_bfloat16* __restrict__ W1l,
                 const float* __restrict__ bias1, const float* __restrict__ indvec,
                 const int* __restrict__ cnt,
                 __half* __restrict__ C0, __nv_bfloat16* __restrict__ C1h,
                 __nv_bfloat16* __restrict__ C1l, int M)
{
    extern __shared__ char smem[];
    __nv_bfloat16* sAh = (__nv_bfloat16*)smem;
    __nv_bfloat16* sAl = sAh + 128 * SROWF;
    __nv_bfloat16* sBh = sAl + 128 * SROWF;
    __nv_bfloat16* sBl = sBh + 128 * SROW;

    const int tid = threadIdx.x;
    const int wid = tid >> 5, lid = tid & 31;
    const int wm = wid >> 1, wn = wid & 1;
    const int g = lid >> 2, tig = lid & 3;
    const int row0 = blockIdx.x * 128;

    // copy full-K A planes once
    #pragma unroll
    for (int t = 0; t < 8; t++) {
        int idx = tid + t * 256;
        int r = idx >> 4, q = idx & 15;
        int rg = row0 + r;
        uint4 h = make_uint4(0, 0, 0, 0), l = make_uint4(0, 0, 0, 0);
        if (rg < M) {
            size_t go = (size_t)rg * H + q * 8;
            h = *(const uint4*)&Ah[go];
            l = *(const uint4*)&Al[go];
        }
        int o = r * SROWF + q * 8;
        *(uint4*)&sAh[o] = h;
        *(uint4*)&sAl[o] = l;
    }

    #pragma unroll
    for (int ws = 0; ws < 2; ws++) {
        const __nv_bfloat16* Wh = ws ? W1h : W0h;
        const __nv_bfloat16* Wl = ws ? W1l : W0l;
        float acc[2][8][4];
        #pragma unroll
        for (int i = 0; i < 2; i++)
            #pragma unroll
            for (int j = 0; j < 8; j++)
                #pragma unroll
                for (int q = 0; q < 4; q++) acc[i][j][q] = 0.f;
        #pragma unroll
        for (int c = 0; c < 2; c++) {
            __syncthreads();
            load_B_pre(Wh, Wl, 128, c * 64, sBh, sBl, tid);
            __syncthreads();
            compute_chunk<SROWF>(sAh, sAl, sBh, sBl, c * 64, wm, wn, g, tig, acc);
        }
        #pragma unroll
        for (int i = 0; i < 2; i++) {
            #pragma unroll
            for (int hf = 0; hf < 2; hf++) {
                int r = row0 + wm * 32 + i * 16 + g + hf * 8;
                if (r >= M) continue;
                bool indf = false;
                if (ws) indf = (cnt[r] > 0);
                #pragma unroll
                for (int j = 0; j < 8; j++) {
                    int col = wn * 64 + j * 8 + tig * 2;
                    float x0 = acc[i][j][hf * 2 + 0];
                    float x1 = acc[i][j][hf * 2 + 1];
                    size_t off = (size_t)r * H + col;
                    if (ws) {
                        x0 += bias1[col]; x1 += bias1[col + 1];
                        if (indf) { x0 += indvec[col]; x1 += indvec[col + 1]; }
                        x0 = fmaxf(x0, 0.f); x1 = fmaxf(x1, 0.f);
                        uint32_t hh, ll;
                        split_pair(x0, x1, hh, ll);
                        *(uint32_t*)&C1h[off] = hh;
                        *(uint32_t*)&C1l[off] = ll;
                    } else {
                        *(__half2*)&C0[off] = __floats2half2_rn(x0, x1);
                    }
                }
            }
        }
    }
}

// ---------------- conv2 movie dual-A (both A from planes, no scaling) ---------
__global__ void __launch_bounds__(256)
gemm_conv2_movie(const __nv_bfloat16* __restrict__ A0h, const __nv_bfloat16* __restrict__ A0l,
                 const __nv_bfloat16* __restrict__ A1h, const __nv_bfloat16* __restrict__ A1l,
                 const __nv_bfloat16* __restrict__ W0h, const __nv_bfloat16* __restrict__ W0l,
                 const __nv_bfloat16* __restrict__ W1h, const __nv_bfloat16* __restrict__ W1l,
                 const float* __restrict__ bias, float* __restrict__ C, int M)
{
    extern __shared__ char smem[];
    __nv_bfloat16* sAh = (__nv_bfloat16*)smem;
    __nv_bfloat16* sAl = sAh + 128 * SROW;
    __nv_bfloat16* sBh = sAl + 128 * SROW;
    __nv_bfloat16* sBl = sBh + 128 * SROW;

    const int tid = threadIdx.x;
    const int wid = tid >> 5, lid = tid & 31;
    const int wm = wid >> 1, wn = wid & 1;
    const int g = lid >> 2, tig = lid & 3;
    const int row0 = blockIdx.x * 128;

    float acc[2][8][4];
    #pragma unroll
    for (int i = 0; i < 2; i++)
        #pragma unroll
        for (int j = 0; j < 8; j++)
            #pragma unroll
            for (int q = 0; q < 4; q++) acc[i][j][q] = 0.f;

    #pragma unroll
    for (int c = 0; c < 4; c++) {
        if (c > 0) __syncthreads();
        const __nv_bfloat16* Ah = (c < 2) ? A0h : A1h;
        const __nv_bfloat16* Al = (c < 2) ? A0l : A1l;
        const __nv_bfloat16* Wh = (c < 2) ? W0h : W1h;
        const __nv_bfloat16* Wl = (c < 2) ? W0l : W1l;
        const int ck = (c & 1) * 64;
        load_A_planes(Ah, Al, 128, ck, row0, M, sAh, sAl, tid);
        load_B_pre(Wh, Wl, 128, ck, sBh, sBl, tid);
        __syncthreads();
        compute_chunk<SROW>(sAh, sAl, sBh, sBl, 0, wm, wn, g, tig, acc);
    }

    #pragma unroll
    for (int i = 0; i < 2; i++) {
        #pragma unroll
        for (int hf = 0; hf < 2; hf++) {
            int r = row0 + wm * 32 + i * 16 + g + hf * 8;
            if (r >= M) continue;
            #pragma unroll
            for (int j = 0; j < 8; j++) {
                int col = wn * 64 + j * 8 + tig * 2;
                float x0 = acc[i][j][hf * 2 + 0] + bias[col];
                float x1 = acc[i][j][hf * 2 + 1] + bias[col + 1];
                *(float2*)&C[(size_t)r * H + col] = make_float2(x0, x1);
            }
        }
    }
}

// ---------------- streams/events: created BEFORE harness checkpoints ----------
static cudaStream_t sCSR = 0, sB = 0;
static cudaEvent_t evFork = 0, evCount = 0, evFill = 0, evC1 = 0, evUH = 0, evUO = 0;
namespace {
struct StreamInit {
    StreamInit() {
        cudaStreamCreateWithFlags(&sCSR, cudaStreamNonBlocking);
        cudaStreamCreateWithFlags(&sB, cudaStreamNonBlocking);
        cudaEventCreateWithFlags(&evFork,  cudaEventDisableTiming);
        cudaEventCreateWithFlags(&evCount, cudaEventDisableTiming);
        cudaEventCreateWithFlags(&evFill,  cudaEventDisableTiming);
        cudaEventCreateWithFlags(&evC1,    cudaEventDisableTiming);
        cudaEventCreateWithFlags(&evUH,    cudaEventDisableTiming);
        cudaEventCreateWithFlags(&evUO,    cudaEventDisableTiming);
        zero_kernel<<<1, 32, 0, sCSR>>>(nullptr, 0);
        zero_kernel<<<1, 32, 0, sB>>>(nullptr, 0);
        zero_kernel<<<1, 32>>>(nullptr, 0);
        cudaEventRecord(evFork, 0);
        cudaStreamWaitEvent(sCSR, evFork, 0);
        cudaDeviceSynchronize();
    }
};
static StreamInit s_stream_init;
}

// ---------------- launch ------------------------------------------------------
static inline int cdiv(int a, int b) { return (a + b - 1) / b; }

extern "C" void kernel_launch(void* const* d_in, const int* in_sizes, int n_in,
                              void* d_out, int out_size)
{
    const float* movie_feats = (const float*)d_in[0];
    const float* user_init   = (const float*)d_in[1];
    const int*   edge_src    = (const int*)d_in[2];
    const int*   edge_dst    = (const int*)d_in[3];
    const int*   lbl_user    = (const int*)d_in[4];
    const int*   lbl_movie   = (const int*)d_in[5];
    const float* Wm    = (const float*)d_in[7];
    const float* bm    = (const float*)d_in[8];
    const float* Wl1um = (const float*)d_in[9];
    const float* bl1um = (const float*)d_in[10];
    const float* Wr1um = (const float*)d_in[11];
    const float* Wl1mu = (const float*)d_in[12];
    const float* bl1mu = (const float*)d_in[13];
    const float* Wr1mu = (const float*)d_in[14];
    const float* Wl2um = (const float*)d_in[15];
    const float* bl2um = (const float*)d_in[16];
    const float* Wr2um = (const float*)d_in[17];
    const float* Wl2mu = (const float*)d_in[18];
    const float* bl2mu = (const float*)d_in[19];
    const float* Wr2mu = (const float*)d_in[20];

    const int E  = in_sizes[2];
    const int EL = in_sizes[4];
    const int NM = in_sizes[0] / FDc;
    const int NU = NUc;
    float* out = (float*)d_out;
    (void)n_in; (void)out_size;

    __nv_bfloat16 *p_mxh, *p_mxl, *p_mhh, *p_mhl, *p_mah, *p_mal, *p_Wth, *p_Wtl;
    float *p_movie_o, *p_userB, *p_cA, *p_d1;
    __half *p_movie_y, *p_movie_z, *p_userH;
    int *p_ucnt, *p_mcnt, *p_uoffs, *p_moffs, *p_ucur, *p_mcur, *p_uadj, *p_madj, *p_ub, *p_mb;
    cudaGetSymbolAddress((void**)&p_mxh, g_mxh);
    cudaGetSymbolAddress((void**)&p_mxl, g_mxl);
    cudaGetSymbolAddress((void**)&p_mhh, g_mhh);
    cudaGetSymbolAddress((void**)&p_mhl, g_mhl);
    cudaGetSymbolAddress((void**)&p_mah, g_mah);
    cudaGetSymbolAddress((void**)&p_mal, g_mal);
    cudaGetSymbolAddress((void**)&p_movie_o, g_movie_o);
    cudaGetSymbolAddress((void**)&p_movie_y, g_movie_y);
    cudaGetSymbolAddress((void**)&p_movie_z, g_movie_z);
    cudaGetSymbolAddress((void**)&p_userH,   g_userH);
    cudaGetSymbolAddress((void**)&p_userB,   g_userB);
    cudaGetSymbolAddress((void**)&p_Wth,     g_Wth);
    cudaGetSymbolAddress((void**)&p_Wtl,     g_Wtl);
    cudaGetSymbolAddress((void**)&p_ucnt,    g_ucnt);
    cudaGetSymbolAddress((void**)&p_mcnt,    g_mcnt);
    cudaGetSymbolAddress((void**)&p_uoffs,   g_uoffs);
    cudaGetSymbolAddress((void**)&p_moffs,   g_moffs);
    cudaGetSymbolAddress((void**)&p_ucur,    g_ucur);
    cudaGetSymbolAddress((void**)&p_mcur,    g_mcur);
    cudaGetSymbolAddress((void**)&p_uadj,    g_uadj);
    cudaGetSymbolAddress((void**)&p_madj,    g_madj);
    cudaGetSymbolAddress((void**)&p_ub,      g_ubsum);
    cudaGetSymbolAddress((void**)&p_mb,      g_mbsum);
    cudaGetSymbolAddress((void**)&p_cA,      g_cA);
    cudaGetSymbolAddress((void**)&p_d1,      g_d1);

    const __nv_bfloat16 *Wm_h = p_Wth,             *Wm_l = p_Wtl;
    const __nv_bfloat16 *l1mu_h = p_Wth + 65536,   *l1mu_l = p_Wtl + 65536;
    const __nv_bfloat16 *r1um_h = l1mu_h + 16384,  *r1um_l = l1mu_l + 16384;
    const __nv_bfloat16 *l2um_h = r1um_h + 16384,  *l2um_l = r1um_l + 16384;
    const __nv_bfloat16 *r2um_h = l2um_h + 16384,  *r2um_l = l2um_l + 16384;
    const __nv_bfloat16 *l2mu_h = r2um_h + 16384,  *l2mu_l = r2um_l + 16384;
    const __nv_bfloat16 *r2mu_h = l2mu_h + 16384,  *r2mu_l = l2mu_l + 16384;

    cudaFuncSetAttribute(gemm_mma<FDc, 0, 2, true,  false>, cudaFuncAttributeMaxDynamicSharedMemorySize, GSMEM);
    cudaFuncSetAttribute(gemm_mma<H,   2, 1, false, false>, cudaFuncAttributeMaxDynamicSharedMemorySize, GSMEM);
    cudaFuncSetAttribute(gemm_mma<H,   1, 0, true,  true >, cudaFuncAttributeMaxDynamicSharedMemorySize, GSMEM);
    cudaFuncSetAttribute(gemm_conv1_movie, cudaFuncAttributeMaxDynamicSharedMemorySize, GSMEM_D2B);
    cudaFuncSetAttribute(gemm_conv2_movie, cudaFuncAttributeMaxDynamicSharedMemorySize, GSMEM);

    const int ZT = 256;

    // ===== main stream: weight prep =====
    prep_weights<<<cdiv(WTOT, 256), 256>>>(Wm, Wl1mu, Wr1um, Wl2um, Wr2um, Wl2mu, Wr2mu);

    // ===== fork CSR build onto sCSR =====
    cudaEventRecord(evFork, 0);
    cudaStreamWaitEvent(sCSR, evFork, 0);
    zero_kernel<<<cdiv(NU / 4, ZT), ZT, 0, sCSR>>>((float*)p_ucnt, NU / 4);
    zero_kernel<<<cdiv(NM / 4, ZT), ZT, 0, sCSR>>>((float*)p_mcnt, NM / 4);
    count_kernel<<<cdiv(E, 256), 256, 0, sCSR>>>(edge_src, edge_dst, E);
    cudaEventRecord(evCount, sCSR);
    int ub = cdiv(NU, 1024), mb = cdiv(NM, 1024);
    scan1_kernel<<<ub, 1024, 0, sCSR>>>(p_ucnt, p_uoffs, p_ub, NU);
    scan1_kernel<<<mb, 1024, 0, sCSR>>>(p_mcnt, p_moffs, p_mb, NM);
    scan2_kernel<<<1, 32, 0, sCSR>>>(p_ub, ub, p_uoffs, NU);
    scan2_kernel<<<1, 32, 0, sCSR>>>(p_mb, mb, p_moffs, NM);
    scan3_kernel<<<cdiv(NU, 256), 256, 0, sCSR>>>(p_uoffs, p_ub, p_ucur, NU);
    scan3_kernel<<<cdiv(NM, 256), 256, 0, sCSR>>>(p_moffs, p_mb, p_mcur, NM);
    fill_kernel<<<cdiv(E, 256), 256, 0, sCSR>>>(edge_src, edge_dst, E);
    cudaEventRecord(evFill, sCSR);

    // ===== main stream: movie_x GEMM (fp32 A, planes out; overlaps CSR) =====
    gemm_mma<FDc, 0, 2, true, false><<<cdiv(NM, 128), 256, GSMEM>>>(
        movie_feats, nullptr, Wm_h, Wm_l, bm, nullptr, p_mxh, p_mxl, NM);
    vec_kernel<<<1, H>>>(user_init, Wl1um, bl1mu, Wr1mu);

    // conv1 (A = movie_x planes; writes movie_y f16 + movie_h planes)
    cudaStreamWaitEvent(0, evCount, 0);
    gemm_conv1_movie<<<cdiv(NM, 128), 256, GSMEM_D2B>>>(
        p_mxh, p_mxl, l1mu_h, l1mu_l, r1um_h, r1um_l, bl1um, p_cA, p_mcnt,
        p_movie_y, p_mhh, p_mhl, NM);
    cudaEventRecord(evC1, 0);

    // user_h gather (fp16 out)
    cudaStreamWaitEvent(0, evFill, 0);
    gather_kernel<1, true, false><<<cdiv(NU * 32, 256), 256>>>(
        p_movie_y, p_uadj, p_uoffs, p_userH, nullptr, p_d1, NU);
    cudaEventRecord(evUH, 0);

    // ===== chain B on sB: movie_z -> uacc(mean) -> user_o =====
    cudaStreamWaitEvent(sB, evC1, 0);
    gemm_mma<H, 2, 1, false, false><<<cdiv(NM, 128), 256, GSMEM, sB>>>(
        p_mhh, p_mhl, l2mu_h, l2mu_l, nullptr, nullptr, p_movie_z, nullptr, NM);
    cudaStreamWaitEvent(sB, evFill, 0);
    gather_kernel<0, false, true><<<cdiv(NU * 32, 256), 256, 0, sB>>>(
        p_movie_z, p_uadj, p_uoffs, p_userB, nullptr, nullptr, NU);
    cudaStreamWaitEvent(sB, evUH, 0);
    gemm_mma<H, 1, 0, true, true><<<cdiv(NU, 128), 256, GSMEM, sB>>>(
        p_userH, nullptr, r2mu_h, r2mu_l, bl2mu, p_userB, p_userB, nullptr, NU);
    cudaEventRecord(evUO, sB);

    // ===== chain A on main: macc(mean -> planes) -> conv2 =====
    gather_kernel<2, false, true><<<cdiv(NM * 32, 256), 256>>>(
        p_userH, p_madj, p_moffs, p_mah, p_mal, nullptr, NM);
    gemm_conv2_movie<<<cdiv(NM, 128), 256, GSMEM>>>(
        p_mah, p_mal, p_mhh, p_mhl, l2um_h, l2um_l, r2um_h, r2um_l, bl2um, p_movie_o, NM);

    // ===== join + dot =====
    cudaStreamWaitEvent(0, evUO, 0);
    dot_kernel<<<cdiv(EL * 32, 256), 256>>>(lbl_user, lbl_movie, p_userB, p_movie_o, out, EL);
}

// round 12
// speedup vs baseline: 1.0425x; 1.0425x over previous
#include <cuda_runtime.h>
#include <cuda_bf16.h>
#include <cuda_fp16.h>
#include <cstdint>

#define H   128
#define NUc 200000
#define NMc 80000
#define FDc 512
#define Ec  2000000

// ---------------- scratch (device globals; no cudaMalloc allowed) ------------
__device__ __nv_bfloat16 g_mxh[NMc * H];   // movie_x hi plane
__device__ __nv_bfloat16 g_mxl[NMc * H];   // movie_x lo plane
__device__ __nv_bfloat16 g_mhh[NMc * H];   // movie_h hi
__device__ __nv_bfloat16 g_mhl[NMc * H];   // movie_h lo
__device__ __nv_bfloat16 g_mah[NMc * H];   // macc-mean hi
__device__ __nv_bfloat16 g_mal[NMc * H];   // macc-mean lo
__device__ __half g_movie_o[NMc * H];      // conv2 movie output (fp16)
__device__ __half g_movie_y[NMc * H];      // conv1 movie_y (fp16)
__device__ __half g_movie_z[NMc * H];      // conv2 movie_z (fp16)
__device__ __half g_userH[NUc * H];        // user_h (fp16)
__device__ __half g_uacc[NUc * H];         // uacc-mean (fp16)
__device__ __half g_userO[NUc * H];        // user_o (fp16)
__device__ int    g_ucnt[NUc];
__device__ int    g_mcnt[NMc];
__device__ int    g_uoffs[NUc + 1];
__device__ int    g_moffs[NMc + 1];
__device__ int    g_ucur[NUc];
__device__ int    g_mcur[NMc];
__device__ int    g_uadj[Ec];
__device__ int    g_madj[Ec];
__device__ int    g_ubsum[256];
__device__ int    g_mbsum[256];
__device__ float  g_cA[H];
__device__ float  g_d1[H];

// pre-split transposed weights: [0,65536)=Wm(K=512); then 6 H x H mats
#define WTOT (65536 + 6 * 16384)
__device__ __nv_bfloat16 g_Wth[WTOT];
__device__ __nv_bfloat16 g_Wtl[WTOT];

// ---------------- split helpers ----------------------------------------------
__device__ __forceinline__ void split_pair(float x0, float x1, uint32_t& hi01, uint32_t& lo01) {
    uint32_t xi = __float_as_uint(x0), yi = __float_as_uint(x1);
    hi01 = __byte_perm(xi, yi, 0x7632);
    float rx = x0 - __uint_as_float(xi & 0xFFFF0000u);
    float ry = x1 - __uint_as_float(yi & 0xFFFF0000u);
    asm("cvt.rn.bf16x2.f32 %0, %1, %2;" : "=r"(lo01) : "f"(ry), "f"(rx));
}
__device__ __forceinline__ void split2(float x, unsigned short& hi, unsigned short& lo) {
    __nv_bfloat16 h = __float2bfloat16(x);
    float hf = __bfloat162float(h);
    __nv_bfloat16 l = __float2bfloat16(x - hf);
    hi = __bfloat16_as_ushort(h);
    lo = __bfloat16_as_ushort(l);
}
__device__ __forceinline__ void mma16816(float* d, const uint32_t* a, uint32_t b0, uint32_t b1) {
    asm volatile("mma.sync.aligned.m16n8k16.row.col.f32.bf16.bf16.f32 "
                 "{%0,%1,%2,%3}, {%4,%5,%6,%7}, {%8,%9}, {%0,%1,%2,%3};\n"
                 : "+f"(d[0]), "+f"(d[1]), "+f"(d[2]), "+f"(d[3])
                 : "r"(a[0]), "r"(a[1]), "r"(a[2]), "r"(a[3]), "r"(b0), "r"(b1));
}

// ---------------- small kernels ----------------------------------------------
__global__ void zero_kernel(float* __restrict__ p, int n4) {
    int i = blockIdx.x * blockDim.x + threadIdx.x;
    if (i < n4) ((float4*)p)[i] = make_float4(0.f, 0.f, 0.f, 0.f);
}
__global__ void prep_weights(const float* __restrict__ Wm,
                             const float* __restrict__ M0, const float* __restrict__ M1,
                             const float* __restrict__ M2, const float* __restrict__ M3,
                             const float* __restrict__ M4, const float* __restrict__ M5) {
    int idx = blockIdx.x * blockDim.x + threadIdx.x;
    if (idx >= WTOT) return;
    const float* src; int K, off;
    if (idx < 65536) { src = Wm; K = 512; off = idx; }
    else {
        int r = idx - 65536;
        int m = r >> 14; off = r & 16383; K = 128;
        src = (m == 0) ? M0 : (m == 1) ? M1 : (m == 2) ? M2 : (m == 3) ? M3 : (m == 4) ? M4 : M5;
    }
    int n = off / K, k = off - n * K;
    float v = src[(size_t)k * H + n];
    unsigned short h, l;
    split2(v, h, l);
    ((unsigned short*)g_Wth)[idx] = h;
    ((unsigned short*)g_Wtl)[idx] = l;
}
__global__ void count_kernel(const int* __restrict__ src, const int* __restrict__ dst, int E) {
    int e = blockIdx.x * blockDim.x + threadIdx.x;
    if (e < E) {
        atomicAdd(&g_ucnt[src[e]], 1);
        atomicAdd(&g_mcnt[dst[e]], 1);
    }
}
__global__ void scan1_kernel(const int* __restrict__ in, int* __restrict__ out,
                             int* __restrict__ bsums, int n) {
    __shared__ int s[1024];
    int i = blockIdx.x * 1024 + threadIdx.x;
    int x = (i < n) ? in[i] : 0;
    s[threadIdx.x] = x;
    __syncthreads();
    #pragma unroll
    for (int d = 1; d < 1024; d <<= 1) {
        int t = (threadIdx.x >= d) ? s[threadIdx.x - d] : 0;
        __syncthreads();
        s[threadIdx.x] += t;
        __syncthreads();
    }
    if (i < n) out[i] = s[threadIdx.x] - x;
    if (threadIdx.x == 1023) bsums[blockIdx.x] = s[1023];
}
__global__ void scan2_kernel(int* __restrict__ bsums, int nb, int* __restrict__ offs, int n) {
    if (threadIdx.x == 0 && blockIdx.x == 0) {
        int run = 0;
        for (int i = 0; i < nb; i++) { int v = bsums[i]; bsums[i] = run; run += v; }
        offs[n] = run;
    }
}
__global__ void scan3_kernel(int* __restrict__ offs, const int* __restrict__ bsums,
                             int* __restrict__ cur, int n) {
    int i = blockIdx.x * blockDim.x + threadIdx.x;
    if (i < n) {
        int v = offs[i] + bsums[i >> 10];
        offs[i] = v;
        cur[i] = v;
    }
}
// user-side adjacency only
__global__ void fill_u_kernel(const int* __restrict__ src, const int* __restrict__ dst, int E) {
    int e = blockIdx.x * blockDim.x + threadIdx.x;
    if (e >= E) return;
    int pu = atomicAdd(&g_ucur[src[e]], 1);
    g_uadj[pu] = dst[e];
}
// movie-side adjacency only
__global__ void fill_m_kernel(const int* __restrict__ src, const int* __restrict__ dst, int E) {
    int e = blockIdx.x * blockDim.x + threadIdx.x;
    if (e >= E) return;
    int pm = atomicAdd(&g_mcur[dst[e]], 1);
    g_madj[pm] = src[e];
}
__global__ void vec_kernel(const float* __restrict__ u0, const float* __restrict__ Wl1um,
                           const float* __restrict__ bl1mu, const float* __restrict__ Wr1mu) {
    int j = threadIdx.x;
    float a = 0.f, b = 0.f;
    for (int k = 0; k < H; k++) {
        float u = u0[k];
        a += u * Wl1um[k * H + j];
        b += u * Wr1mu[k * H + j];
    }
    g_cA[j] = a;
    g_d1[j] = b + bl1mu[j];
}

// warp-per-node CSR gather over fp16 rows: 16 lanes x 16B, 2 rows/iter.
// OUTK: 0=f32, 1=f16, 2=bf16 hi/lo planes. FUSED1: mean+d1+relu. MEAN: mean only.
template<int OUTK, bool FUSED1, bool MEAN>
__global__ void gather_kernel(const __half* __restrict__ rows, const int* __restrict__ adj,
                              const int* __restrict__ offs, void* __restrict__ out,
                              void* __restrict__ outl, const float* __restrict__ d1, int N)
{
    int node = (blockIdx.x * blockDim.x + threadIdx.x) >> 5;
    int lane = threadIdx.x & 31;
    if (node >= N) return;
    int beg = offs[node], end = offs[node + 1];
    int hsel = lane >> 4;
    int sub  = lane & 15;
    float acc[8];
    #pragma unroll
    for (int j = 0; j < 8; j++) acc[j] = 0.f;

    for (int base = beg; base < end; base += 32) {
        int nn = min(32, end - base);
        int myidx = (lane < nn) ? __ldg(&adj[base + lane]) : 0;
        int np = (nn + 1) >> 1;
        #pragma unroll 4
        for (int t = 0; t < np; t++) {
            int sel = 2 * t + hsel;
            int ii = __shfl_sync(0xffffffffu, myidx, sel & 31);
            if (sel < nn) {
                uint4 v = *(const uint4*)&rows[(size_t)ii * H + sub * 8];
                float2 f0 = __half22float2(*(__half2*)&v.x);
                float2 f1 = __half22float2(*(__half2*)&v.y);
                float2 f2 = __half22float2(*(__half2*)&v.z);
                float2 f3 = __half22float2(*(__half2*)&v.w);
                acc[0] += f0.x; acc[1] += f0.y; acc[2] += f1.x; acc[3] += f1.y;
                acc[4] += f2.x; acc[5] += f2.y; acc[6] += f3.x; acc[7] += f3.y;
            }
        }
    }
    #pragma unroll
    for (int j = 0; j < 8; j++) acc[j] += __shfl_xor_sync(0xffffffffu, acc[j], 16);

    if (lane < 16) {
        if (FUSED1) {
            float rinv = 1.f / fmaxf((float)(end - beg), 1.f);
            float4 d0 = *(const float4*)&d1[sub * 8];
            float4 d4 = *(const float4*)&d1[sub * 8 + 4];
            acc[0] = fmaxf(acc[0] * rinv + d0.x, 0.f);
            acc[1] = fmaxf(acc[1] * rinv + d0.y, 0.f);
            acc[2] = fmaxf(acc[2] * rinv + d0.z, 0.f);
            acc[3] = fmaxf(acc[3] * rinv + d0.w, 0.f);
            acc[4] = fmaxf(acc[4] * rinv + d4.x, 0.f);
            acc[5] = fmaxf(acc[5] * rinv + d4.y, 0.f);
            acc[6] = fmaxf(acc[6] * rinv + d4.z, 0.f);
            acc[7] = fmaxf(acc[7] * rinv + d4.w, 0.f);
        } else if (MEAN) {
            float rinv = 1.f / fmaxf((float)(end - beg), 1.f);
            #pragma unroll
            for (int j = 0; j < 8; j++) acc[j] *= rinv;
        }
        size_t off = (size_t)node * H + sub * 8;
        if (OUTK == 1) {
            uint4 pk;
            *(__half2*)&pk.x = __floats2half2_rn(acc[0], acc[1]);
            *(__half2*)&pk.y = __floats2half2_rn(acc[2], acc[3]);
            *(__half2*)&pk.z = __floats2half2_rn(acc[4], acc[5]);
            *(__half2*)&pk.w = __floats2half2_rn(acc[6], acc[7]);
            *(uint4*)&((__half*)out)[off] = pk;
        } else if (OUTK == 2) {
            uint4 ph, pl;
            split_pair(acc[0], acc[1], ph.x, pl.x);
            split_pair(acc[2], acc[3], ph.y, pl.y);
            split_pair(acc[4], acc[5], ph.z, pl.z);
            split_pair(acc[6], acc[7], ph.w, pl.w);
            *(uint4*)&((__nv_bfloat16*)out)[off]  = ph;
            *(uint4*)&((__nv_bfloat16*)outl)[off] = pl;
        } else {
            float* o = &((float*)out)[off];
            *(float4*)o       = make_float4(acc[0], acc[1], acc[2], acc[3]);
            *(float4*)(o + 4) = make_float4(acc[4], acc[5], acc[6], acc[7]);
        }
    }
}

// dot over fp16 feature tables: warp per edge, uint2 (4 halves) per lane
__global__ void dot_kernel(const int* __restrict__ lu, const int* __restrict__ lm,
                           const __half* __restrict__ uo, const __half* __restrict__ mo,
                           float* __restrict__ out, int EL) {
    int gw = (blockIdx.x * blockDim.x + threadIdx.x) >> 5;
    int lane = threadIdx.x & 31;
    if (gw >= EL) return;
    int u = __ldg(&lu[gw]);
    int m = __ldg(&lm[gw]);
    uint2 av = *(const uint2*)&uo[(size_t)u * H + lane * 4];
    uint2 bv = *(const uint2*)&mo[(size_t)m * H + lane * 4];
    float2 a0 = __half22float2(*(__half2*)&av.x), a1 = __half22float2(*(__half2*)&av.y);
    float2 b0 = __half22float2(*(__half2*)&bv.x), b1 = __half22float2(*(__half2*)&bv.y);
    float s = a0.x * b0.x + a0.y * b0.y + a1.x * b1.x + a1.y * b1.y;
    #pragma unroll
    for (int o = 16; o; o >>= 1) s += __shfl_xor_sync(0xffffffffu, s, o);
    if (lane == 0) out[gw] = s;
}

// ---------------- GEMM common -------------------------------------------------
#define SROW 72
#define SROWF 136
#define GSMEM (4 * 128 * SROW * 2 + 512)
#define GSMEM_D2B (2 * 128 * SROWF * 2 + 2 * 128 * SROW * 2 + 512)

__device__ __forceinline__ void load_B_pre(const __nv_bfloat16* __restrict__ Wth,
                                           const __nv_bfloat16* __restrict__ Wtl,
                                           int K, int kbase,
                                           __nv_bfloat16* sBh, __nv_bfloat16* sBl, int tid) {
    #pragma unroll
    for (int t = 0; t < 4; t++) {
        int idx = tid + t * 256;
        int n = idx >> 3, kq = idx & 7;
        size_t go = (size_t)n * K + kbase + kq * 8;
        uint4 h = *(const uint4*)&Wth[go];
        uint4 l = *(const uint4*)&Wtl[go];
        int o = n * SROW + kq * 8;
        *(uint4*)&sBh[o] = h;
        *(uint4*)&sBl[o] = l;
    }
}
__device__ __forceinline__ void load_A_planes(const __nv_bfloat16* __restrict__ Ah,
                                              const __nv_bfloat16* __restrict__ Al,
                                              int KTOT, int kbase, int row0, int M,
                                              __nv_bfloat16* sAh, __nv_bfloat16* sAl, int tid) {
    #pragma unroll
    for (int t = 0; t < 4; t++) {
        int idx = tid + t * 256;
        int r = idx >> 3, q = idx & 7;
        int rg = row0 + r;
        uint4 h = make_uint4(0, 0, 0, 0), l = make_uint4(0, 0, 0, 0);
        if (rg < M) {
            size_t go = (size_t)rg * KTOT + kbase + q * 8;
            h = *(const uint4*)&Ah[go];
            l = *(const uint4*)&Al[go];
        }
        int o = r * SROW + q * 8;
        *(uint4*)&sAh[o] = h;
        *(uint4*)&sAl[o] = l;
    }
}

template<int AST>
__device__ __forceinline__ void compute_chunk(const __nv_bfloat16* sAh, const __nv_bfloat16* sAl,
                                              const __nv_bfloat16* sBh, const __nv_bfloat16* sBl,
                                              int akof, int wm, int wn, int g, int tig,
                                              float acc[2][8][4]) {
    #pragma unroll
    for (int ks = 0; ks < 4; ks++) {
        int kof = ks * 16 + tig * 2;
        uint32_t ah[2][4], al[2][4];
        #pragma unroll
        for (int i = 0; i < 2; i++) {
            int r0 = (wm * 32 + i * 16 + g) * AST + akof + kof;
            int r1 = r0 + 8 * AST;
            ah[i][0] = *(const uint32_t*)&sAh[r0];
            ah[i][1] = *(const uint32_t*)&sAh[r1];
            ah[i][2] = *(const uint32_t*)&sAh[r0 + 8];
            ah[i][3] = *(const uint32_t*)&sAh[r1 + 8];
            al[i][0] = *(const uint32_t*)&sAl[r0];
            al[i][1] = *(const uint32_t*)&sAl[r1];
            al[i][2] = *(const uint32_t*)&sAl[r0 + 8];
            al[i][3] = *(const uint32_t*)&sAl[r1 + 8];
        }
        #pragma unroll
        for (int j = 0; j < 8; j++) {
            int nb = (wn * 64 + j * 8 + g) * SROW + kof;
            uint32_t bh0 = *(const uint32_t*)&sBh[nb];
            uint32_t bh1 = *(const uint32_t*)&sBh[nb + 8];
            uint32_t bl0 = *(const uint32_t*)&sBl[nb];
            uint32_t bl1 = *(const uint32_t*)&sBl[nb + 8];
            mma16816(acc[0][j], ah[0], bh0, bh1);
            mma16816(acc[1][j], ah[1], bh0, bh1);
            mma16816(acc[0][j], ah[0], bl0, bl1);
            mma16816(acc[1][j], ah[1], bl0, bl1);
            mma16816(acc[0][j], al[0], bh0, bh1);
            mma16816(acc[1][j], al[1], bh0, bh1);
        }
    }
}

// ---------------- generic GEMM ------------------------------------------------
// AK: 0=f32 (cheap split), 1=f16 (cheap split), 2=planes
// CK: 0=f32, 1=f16, 2=planes ; ADDM: 0=none, 1=f32, 2=f16
template<int KTOT, int AK, int CK, bool BIAS, int ADDM>
__global__ void __launch_bounds__(256)
gemm_mma(const void* __restrict__ Av, const void* __restrict__ Avl,
         const __nv_bfloat16* __restrict__ Wth, const __nv_bfloat16* __restrict__ Wtl,
         const float* __restrict__ bias, const void* __restrict__ addmat,
         void* __restrict__ Cv, void* __restrict__ Cvl, int M)
{
    extern __shared__ char smem[];
    __nv_bfloat16* sAh = (__nv_bfloat16*)smem;
    __nv_bfloat16* sAl = sAh + 128 * SROW;
    __nv_bfloat16* sBh = sAl + 128 * SROW;
    __nv_bfloat16* sBl = sBh + 128 * SROW;

    const int tid = threadIdx.x;
    const int wid = tid >> 5, lid = tid & 31;
    const int wm = wid >> 1, wn = wid & 1;
    const int g = lid >> 2, tig = lid & 3;
    const int row0 = blockIdx.x * 128;

    float acc[2][8][4];
    #pragma unroll
    for (int i = 0; i < 2; i++)
        #pragma unroll
        for (int j = 0; j < 8; j++)
            #pragma unroll
            for (int q = 0; q < 4; q++) acc[i][j][q] = 0.f;

    const int NCH = KTOT / 64;
    for (int c = 0; c < NCH; c++) {
        if (c > 0) __syncthreads();
        if (AK == 2) {
            load_A_planes((const __nv_bfloat16*)Av, (const __nv_bfloat16*)Avl,
                          KTOT, c * 64, row0, M, sAh, sAl, tid);
        } else {
            #pragma unroll
            for (int t = 0; t < 8; t++) {
                int idx = tid + t * 256;
                int r = idx >> 4, q = idx & 15;
                int rg = row0 + r;
                float4 v = make_float4(0.f, 0.f, 0.f, 0.f);
                if (rg < M) {
                    if (AK == 1) {
                        const __half* A = (const __half*)Av;
                        uint2 hv = *(const uint2*)&A[(size_t)rg * KTOT + c * 64 + q * 4];
                        float2 f0 = __half22float2(*(__half2*)&hv.x);
                        float2 f1 = __half22float2(*(__half2*)&hv.y);
                        v = make_float4(f0.x, f0.y, f1.x, f1.y);
                    } else {
                        v = *(const float4*)&((const float*)Av)[(size_t)rg * KTOT + c * 64 + q * 4];
                    }
                }
                uint2 hp, lp;
                split_pair(v.x, v.y, hp.x, lp.x);
                split_pair(v.z, v.w, hp.y, lp.y);
                int o = r * SROW + q * 4;
                *(uint2*)&sAh[o] = hp;
                *(uint2*)&sAl[o] = lp;
            }
        }
        load_B_pre(Wth, Wtl, KTOT, c * 64, sBh, sBl, tid);
        __syncthreads();
        compute_chunk<SROW>(sAh, sAl, sBh, sBl, 0, wm, wn, g, tig, acc);
    }

    #pragma unroll
    for (int i = 0; i < 2; i++) {
        #pragma unroll
        for (int hf = 0; hf < 2; hf++) {
            int r = row0 + wm * 32 + i * 16 + g + hf * 8;
            if (r >= M) continue;
            #pragma unroll
            for (int j = 0; j < 8; j++) {
                int col = wn * 64 + j * 8 + tig * 2;
                float x0 = acc[i][j][hf * 2 + 0];
                float x1 = acc[i][j][hf * 2 + 1];
                if (BIAS) { x0 += bias[col]; x1 += bias[col + 1]; }
                size_t off = (size_t)r * H + col;
                if (ADDM == 1) {
                    float2 m = *(const float2*)&((const float*)addmat)[off];
                    x0 += m.x; x1 += m.y;
                } else if (ADDM == 2) {
                    uint32_t mv = *(const uint32_t*)&((const __half*)addmat)[off];
                    float2 m = __half22float2(*(__half2*)&mv);
                    x0 += m.x; x1 += m.y;
                }
                if (CK == 1) {
                    *(__half2*)&((__half*)Cv)[off] = __floats2half2_rn(x0, x1);
                } else if (CK == 2) {
                    uint32_t hh, ll;
                    split_pair(x0, x1, hh, ll);
                    *(uint32_t*)&((__nv_bfloat16*)Cv)[off]  = hh;
                    *(uint32_t*)&((__nv_bfloat16*)Cvl)[off] = ll;
                } else {
                    *(float2*)&((float*)Cv)[off] = make_float2(x0, x1);
                }
            }
        }
    }
}

// ---------------- conv1 movie dual-B (A = movie_x planes) ---------------------
__global__ void __launch_bounds__(256)
gemm_conv1_movie(const __nv_bfloat16* __restrict__ Ah, const __nv_bfloat16* __restrict__ Al,
                 const __nv_bfloat16* __restrict__ W0h, const __nv_bfloat16* __restrict__ W0l,
                 const __nv_bfloat16* __restrict__ W1h, const __nv_bfloat16* __restrict__ W1l,
                 const float* __restrict__ bias1, const float* __restrict__ indvec,
                 const int* __restrict__ cnt,
                 __half* __restrict__ C0, __nv_bfloat16* __restrict__ C1h,
                 __nv_bfloat16* __restrict__ C1l, int M)
{
    extern __shared__ char smem[];
    __nv_bfloat16* sAh = (__nv_bfloat16*)smem;
    __nv_bfloat16* sAl = sAh + 128 * SROWF;
    __nv_bfloat16* sBh = sAl + 128 * SROWF;
    __nv_bfloat16* sBl = sBh + 128 * SROW;

    const int tid = threadIdx.x;
    const int wid = tid >> 5, lid = tid & 31;
    const int wm = wid >> 1, wn = wid & 1;
    const int g = lid >> 2, tig = lid & 3;
    const int row0 = blockIdx.x * 128;

    #pragma unroll
    for (int t = 0; t < 8; t++) {
        int idx = tid + t * 256;
        int r = idx >> 4, q = idx & 15;
        int rg = row0 + r;
        uint4 h = make_uint4(0, 0, 0, 0), l = make_uint4(0, 0, 0, 0);
        if (rg < M) {
            size_t go = (size_t)rg * H + q * 8;
            h = *(const uint4*)&Ah[go];
            l = *(const uint4*)&Al[go];
        }
        int o = r * SROWF + q * 8;
        *(uint4*)&sAh[o] = h;
        *(uint4*)&sAl[o] = l;
    }

    #pragma unroll
    for (int ws = 0; ws < 2; ws++) {
        const __nv_bfloat16* Wh = ws ? W1h : W0h;
        const __nv_bfloat16* Wl = ws ? W1l : W0l;
        float acc[2][8][4];
        #pragma unroll
        for (int i = 0; i < 2; i++)
            #pragma unroll
            for (int j = 0; j < 8; j++)
                #pragma unroll
                for (int q = 0; q < 4; q++) acc[i][j][q] = 0.f;
        #pragma unroll
        for (int c = 0; c < 2; c++) {
            __syncthreads();
            load_B_pre(Wh, Wl, 128, c * 64, sBh, sBl, tid);
            __syncthreads();
            compute_chunk<SROWF>(sAh, sAl, sBh, sBl, c * 64, wm, wn, g, tig, acc);
        }
        #pragma unroll
        for (int i = 0; i < 2; i++) {
            #pragma unroll
            for (int hf = 0; hf < 2; hf++) {
                int r = row0 + wm * 32 + i * 16 + g + hf * 8;
                if (r >= M) continue;
                bool indf = false;
                if (ws) indf = (cnt[r] > 0);
                #pragma unroll
                for (int j = 0; j < 8; j++) {
                    int col = wn * 64 + j * 8 + tig * 2;
                    float x0 = acc[i][j][hf * 2 + 0];
                    float x1 = acc[i][j][hf * 2 + 1];
                    size_t off = (size_t)r * H + col;
                    if (ws) {
                        x0 += bias1[col]; x1 += bias1[col + 1];
                        if (indf) { x0 += indvec[col]; x1 += indvec[col + 1]; }
                        x0 = fmaxf(x0, 0.f); x1 = fmaxf(x1, 0.f);
                        uint32_t hh, ll;
                        split_pair(x0, x1, hh, ll);
                        *(uint32_t*)&C1h[off] = hh;
                        *(uint32_t*)&C1l[off] = ll;
                    } else {
                        *(__half2*)&C0[off] = __floats2half2_rn(x0, x1);
                    }
                }
            }
        }
    }
}

// ---------------- conv2 movie dual-A (planes in, fp16 out) --------------------
__global__ void __launch_bounds__(256)
gemm_conv2_movie(const __nv_bfloat16* __restrict__ A0h, const __nv_bfloat16* __restrict__ A0l,
                 const __nv_bfloat16* __restrict__ A1h, const __nv_bfloat16* __restrict__ A1l,
                 const __nv_bfloat16* __restrict__ W0h, const __nv_bfloat16* __restrict__ W0l,
                 const __nv_bfloat16* __restrict__ W1h, const __nv_bfloat16* __restrict__ W1l,
                 const float* __restrict__ bias, __half* __restrict__ C, int M)
{
    extern __shared__ char smem[];
    __nv_bfloat16* sAh = (__nv_bfloat16*)smem;
    __nv_bfloat16* sAl = sAh + 128 * SROW;
    __nv_bfloat16* sBh = sAl + 128 * SROW;
    __nv_bfloat16* sBl = sBh + 128 * SROW;

    const int tid = threadIdx.x;
    const int wid = tid >> 5, lid = tid & 31;
    const int wm = wid >> 1, wn = wid & 1;
    const int g = lid >> 2, tig = lid & 3;
    const int row0 = blockIdx.x * 128;

    float acc[2][8][4];
    #pragma unroll
    for (int i = 0; i < 2; i++)
        #pragma unroll
        for (int j = 0; j < 8; j++)
            #pragma unroll
            for (int q = 0; q < 4; q++) acc[i][j][q] = 0.f;

    #pragma unroll
    for (int c = 0; c < 4; c++) {
        if (c > 0) __syncthreads();
        const __nv_bfloat16* Ah = (c < 2) ? A0h : A1h;
        const __nv_bfloat16* Al = (c < 2) ? A0l : A1l;
        const __nv_bfloat16* Wh = (c < 2) ? W0h : W1h;
        const __nv_bfloat16* Wl = (c < 2) ? W0l : W1l;
        const int ck = (c & 1) * 64;
        load_A_planes(Ah, Al, 128, ck, row0, M, sAh, sAl, tid);
        load_B_pre(Wh, Wl, 128, ck, sBh, sBl, tid);
        __syncthreads();
        compute_chunk<SROW>(sAh, sAl, sBh, sBl, 0, wm, wn, g, tig, acc);
    }

    #pragma unroll
    for (int i = 0; i < 2; i++) {
        #pragma unroll
        for (int hf = 0; hf < 2; hf++) {
            int r = row0 + wm * 32 + i * 16 + g + hf * 8;
            if (r >= M) continue;
            #pragma unroll
            for (int j = 0; j < 8; j++) {
                int col = wn * 64 + j * 8 + tig * 2;
                float x0 = acc[i][j][hf * 2 + 0] + bias[col];
                float x1 = acc[i][j][hf * 2 + 1] + bias[col + 1];
                *(__half2*)&C[(size_t)r * H + col] = __floats2half2_rn(x0, x1);
            }
        }
    }
}

// ---------------- streams/events: created BEFORE harness checkpoints ----------
static cudaStream_t sCSR = 0, sB = 0;
static cudaEvent_t evFork = 0, evCount = 0, evFillU = 0, evFillM = 0, evC1 = 0, evUH = 0, evUO = 0;
namespace {
struct StreamInit {
    StreamInit() {
        cudaStreamCreateWithFlags(&sCSR, cudaStreamNonBlocking);
        cudaStreamCreateWithFlags(&sB, cudaStreamNonBlocking);
        cudaEventCreateWithFlags(&evFork,  cudaEventDisableTiming);
        cudaEventCreateWithFlags(&evCount, cudaEventDisableTiming);
        cudaEventCreateWithFlags(&evFillU, cudaEventDisableTiming);
        cudaEventCreateWithFlags(&evFillM, cudaEventDisableTiming);
        cudaEventCreateWithFlags(&evC1,    cudaEventDisableTiming);
        cudaEventCreateWithFlags(&evUH,    cudaEventDisableTiming);
        cudaEventCreateWithFlags(&evUO,    cudaEventDisableTiming);
        zero_kernel<<<1, 32, 0, sCSR>>>(nullptr, 0);
        zero_kernel<<<1, 32, 0, sB>>>(nullptr, 0);
        zero_kernel<<<1, 32>>>(nullptr, 0);
        cudaEventRecord(evFork, 0);
        cudaStreamWaitEvent(sCSR, evFork, 0);
        cudaDeviceSynchronize();
    }
};
static StreamInit s_stream_init;
}

// ---------------- launch ------------------------------------------------------
static inline int cdiv(int a, int b) { return (a + b - 1) / b; }

extern "C" void kernel_launch(void* const* d_in, const int* in_sizes, int n_in,
                              void* d_out, int out_size)
{
    const float* movie_feats = (const float*)d_in[0];
    const float* user_init   = (const float*)d_in[1];
    const int*   edge_src    = (const int*)d_in[2];
    const int*   edge_dst    = (const int*)d_in[3];
    const int*   lbl_user    = (const int*)d_in[4];
    const int*   lbl_movie   = (const int*)d_in[5];
    const float* Wm    = (const float*)d_in[7];
    const float* bm    = (const float*)d_in[8];
    const float* Wl1um = (const float*)d_in[9];
    const float* bl1um = (const float*)d_in[10];
    const float* Wr1um = (const float*)d_in[11];
    const float* Wl1mu = (const float*)d_in[12];
    const float* bl1mu = (const float*)d_in[13];
    const float* Wr1mu = (const float*)d_in[14];
    const float* Wl2um = (const float*)d_in[15];
    const float* bl2um = (const float*)d_in[16];
    const float* Wr2um = (const float*)d_in[17];
    const float* Wl2mu = (const float*)d_in[18];
    const float* bl2mu = (const float*)d_in[19];
    const float* Wr2mu = (const float*)d_in[20];

    const int E  = in_sizes[2];
    const int EL = in_sizes[4];
    const int NM = in_sizes[0] / FDc;
    const int NU = NUc;
    float* out = (float*)d_out;
    (void)n_in; (void)out_size;

    __nv_bfloat16 *p_mxh, *p_mxl, *p_mhh, *p_mhl, *p_mah, *p_mal, *p_Wth, *p_Wtl;
    float *p_cA, *p_d1;
    __half *p_movie_o, *p_movie_y, *p_movie_z, *p_userH, *p_uacc, *p_userO;
    int *p_ucnt, *p_mcnt, *p_uoffs, *p_moffs, *p_ucur, *p_mcur, *p_uadj, *p_madj, *p_ub, *p_mb;
    cudaGetSymbolAddress((void**)&p_mxh, g_mxh);
    cudaGetSymbolAddress((void**)&p_mxl, g_mxl);
    cudaGetSymbolAddress((void**)&p_mhh, g_mhh);
    cudaGetSymbolAddress((void**)&p_mhl, g_mhl);
    cudaGetSymbolAddress((void**)&p_mah, g_mah);
    cudaGetSymbolAddress((void**)&p_mal, g_mal);
    cudaGetSymbolAddress((void**)&p_movie_o, g_movie_o);
    cudaGetSymbolAddress((void**)&p_movie_y, g_movie_y);
    cudaGetSymbolAddress((void**)&p_movie_z, g_movie_z);
    cudaGetSymbolAddress((void**)&p_userH,   g_userH);
    cudaGetSymbolAddress((void**)&p_uacc,    g_uacc);
    cudaGetSymbolAddress((void**)&p_userO,   g_userO);
    cudaGetSymbolAddress((void**)&p_Wth,     g_Wth);
    cudaGetSymbolAddress((void**)&p_Wtl,     g_Wtl);
    cudaGetSymbolAddress((void**)&p_ucnt,    g_ucnt);
    cudaGetSymbolAddress((void**)&p_mcnt,    g_mcnt);
    cudaGetSymbolAddress((void**)&p_uoffs,   g_uoffs);
    cudaGetSymbolAddress((void**)&p_moffs,   g_moffs);
    cudaGetSymbolAddress((void**)&p_ucur,    g_ucur);
    cudaGetSymbolAddress((void**)&p_mcur,    g_mcur);
    cudaGetSymbolAddress((void**)&p_uadj,    g_uadj);
    cudaGetSymbolAddress((void**)&p_madj,    g_madj);
    cudaGetSymbolAddress((void**)&p_ub,      g_ubsum);
    cudaGetSymbolAddress((void**)&p_mb,      g_mbsum);
    cudaGetSymbolAddress((void**)&p_cA,      g_cA);
    cudaGetSymbolAddress((void**)&p_d1,      g_d1);

    const __nv_bfloat16 *Wm_h = p_Wth,             *Wm_l = p_Wtl;
    const __nv_bfloat16 *l1mu_h = p_Wth + 65536,   *l1mu_l = p_Wtl + 65536;
    const __nv_bfloat16 *r1um_h = l1mu_h + 16384,  *r1um_l = l1mu_l + 16384;
    const __nv_bfloat16 *l2um_h = r1um_h + 16384,  *l2um_l = r1um_l + 16384;
    const __nv_bfloat16 *r2um_h = l2um_h + 16384,  *r2um_l = l2um_l + 16384;
    const __nv_bfloat16 *l2mu_h = r2um_h + 16384,  *l2mu_l = r2um_l + 16384;
    const __nv_bfloat16 *r2mu_h = l2mu_h + 16384,  *r2mu_l = l2mu_l + 16384;

    cudaFuncSetAttribute(gemm_mma<FDc, 0, 2, true,  0>, cudaFuncAttributeMaxDynamicSharedMemorySize, GSMEM);
    cudaFuncSetAttribute(gemm_mma<H,   2, 1, false, 0>, cudaFuncAttributeMaxDynamicSharedMemorySize, GSMEM);
    cudaFuncSetAttribute(gemm_mma<H,   1, 1, true,  2>, cudaFuncAttributeMaxDynamicSharedMemorySize, GSMEM);
    cudaFuncSetAttribute(gemm_conv1_movie, cudaFuncAttributeMaxDynamicSharedMemorySize, GSMEM_D2B);
    cudaFuncSetAttribute(gemm_conv2_movie, cudaFuncAttributeMaxDynamicSharedMemorySize, GSMEM);

    const int ZT = 256;

    // ===== main stream: weight prep =====
    prep_weights<<<cdiv(WTOT, 256), 256>>>(Wm, Wl1mu, Wr1um, Wl2um, Wr2um, Wl2mu, Wr2mu);

    // ===== fork CSR build onto sCSR =====
    cudaEventRecord(evFork, 0);
    cudaStreamWaitEvent(sCSR, evFork, 0);
    zero_kernel<<<cdiv(NU / 4, ZT), ZT, 0, sCSR>>>((float*)p_ucnt, NU / 4);
    zero_kernel<<<cdiv(NM / 4, ZT), ZT, 0, sCSR>>>((float*)p_mcnt, NM / 4);
    count_kernel<<<cdiv(E, 256), 256, 0, sCSR>>>(edge_src, edge_dst, E);
    cudaEventRecord(evCount, sCSR);
    int ub = cdiv(NU, 1024), mb = cdiv(NM, 1024);
    scan1_kernel<<<ub, 1024, 0, sCSR>>>(p_ucnt, p_uoffs, p_ub, NU);
    scan2_kernel<<<1, 32, 0, sCSR>>>(p_ub, ub, p_uoffs, NU);
    scan3_kernel<<<cdiv(NU, 256), 256, 0, sCSR>>>(p_uoffs, p_ub, p_ucur, NU);
    fill_u_kernel<<<cdiv(E, 256), 256, 0, sCSR>>>(edge_src, edge_dst, E);
    cudaEventRecord(evFillU, sCSR);
    scan1_kernel<<<mb, 1024, 0, sCSR>>>(p_mcnt, p_moffs, p_mb, NM);
    scan2_kernel<<<1, 32, 0, sCSR>>>(p_mb, mb, p_moffs, NM);
    scan3_kernel<<<cdiv(NM, 256), 256, 0, sCSR>>>(p_moffs, p_mb, p_mcur, NM);
    fill_m_kernel<<<cdiv(E, 256), 256, 0, sCSR>>>(edge_src, edge_dst, E);
    cudaEventRecord(evFillM, sCSR);

    // ===== main stream: movie_x GEMM (overlaps CSR) =====
    gemm_mma<FDc, 0, 2, true, 0><<<cdiv(NM, 128), 256, GSMEM>>>(
        movie_feats, nullptr, Wm_h, Wm_l, bm, nullptr, p_mxh, p_mxl, NM);
    vec_kernel<<<1, H>>>(user_init, Wl1um, bl1mu, Wr1mu);

    // conv1 (A = movie_x planes; writes movie_y f16 + movie_h planes)
    cudaStreamWaitEvent(0, evCount, 0);
    gemm_conv1_movie<<<cdiv(NM, 128), 256, GSMEM_D2B>>>(
        p_mxh, p_mxl, l1mu_h, l1mu_l, r1um_h, r1um_l, bl1um, p_cA, p_mcnt,
        p_movie_y, p_mhh, p_mhl, NM);
    cudaEventRecord(evC1, 0);

    // user_h gather (fp16 out) — waits only on user-side fill
    cudaStreamWaitEvent(0, evFillU, 0);
    gather_kernel<1, true, false><<<cdiv(NU * 32, 256), 256>>>(
        p_movie_y, p_uadj, p_uoffs, p_userH, nullptr, p_d1, NU);
    cudaEventRecord(evUH, 0);

    // ===== chain B on sB: movie_z -> uacc(mean,f16) -> user_o(f16) =====
    cudaStreamWaitEvent(sB, evC1, 0);
    gemm_mma<H, 2, 1, false, 0><<<cdiv(NM, 128), 256, GSMEM, sB>>>(
        p_mhh, p_mhl, l2mu_h, l2mu_l, nullptr, nullptr, p_movie_z, nullptr, NM);
    cudaStreamWaitEvent(sB, evFillU, 0);
    gather_kernel<1, false, true><<<cdiv(NU * 32, 256), 256, 0, sB>>>(
        p_movie_z, p_uadj, p_uoffs, p_uacc, nullptr, nullptr, NU);
    cudaStreamWaitEvent(sB, evUH, 0);
    gemm_mma<H, 1, 1, true, 2><<<cdiv(NU, 128), 256, GSMEM, sB>>>(
        p_userH, nullptr, r2mu_h, r2mu_l, bl2mu, p_uacc, p_userO, nullptr, NU);
    cudaEventRecord(evUO, sB);

    // ===== chain A on main: macc(mean -> planes) -> conv2 (fp16 out) =====
    cudaStreamWaitEvent(0, evFillM, 0);
    gather_kernel<2, false, true><<<cdiv(NM * 32, 256), 256>>>(
        p_userH, p_madj, p_moffs, p_mah, p_mal, nullptr, NM);
    gemm_conv2_movie<<<cdiv(NM, 128), 256, GSMEM>>>(
        p_mah, p_mal, p_mhh, p_mhl, l2um_h, l2um_l, r2um_h, r2um_l, bl2um, p_movie_o, NM);

    // ===== join + dot (fp16 feature tables) =====
    cudaStreamWaitEvent(0, evUO, 0);
    dot_kernel<<<cdiv(EL * 32, 256), 256>>>(lbl_user, lbl_movie, p_userO, p_movie_o, out, EL);
}

// round 13
// speedup vs baseline: 1.0668x; 1.0233x over previous
#include <cuda_runtime.h>
#include <cuda_bf16.h>
#include <cuda_fp16.h>
#include <cstdint>

#define H   128
#define NUc 200000
#define NMc 80000
#define FDc 512
#define Ec  2000000

// ---------------- scratch (device globals; no cudaMalloc allowed) ------------
__device__ __nv_bfloat16 g_mxh[NMc * H];   // movie_x hi plane
__device__ __nv_bfloat16 g_mxl[NMc * H];   // movie_x lo plane
__device__ __nv_bfloat16 g_mhh[NMc * H];   // movie_h hi
__device__ __nv_bfloat16 g_mhl[NMc * H];   // movie_h lo
__device__ __nv_bfloat16 g_mah[NMc * H];   // macc-mean hi
__device__ __nv_bfloat16 g_mal[NMc * H];   // macc-mean lo
__device__ __half g_movie_o[NMc * H];      // conv2 movie output (fp16)
__device__ __half g_movie_y[NMc * H];      // conv1 movie_y (fp16)
__device__ __half g_movie_z[NMc * H];      // conv2 movie_z (fp16)
__device__ __half g_userH[NUc * H];        // user_h (fp16)
__device__ __half g_uacc[NUc * H];         // uacc-mean (fp16)
__device__ __half g_userO[NUc * H];        // user_o (fp16)
__device__ int    g_ucnt[NUc];
__device__ int    g_mcnt[NMc];
__device__ int    g_uoffs[NUc + 1];
__device__ int    g_moffs[NMc + 1];
__device__ int    g_ucur[NUc];
__device__ int    g_mcur[NMc];
__device__ int    g_uadj[Ec];
__device__ int    g_madj[Ec];
__device__ int    g_ubsum[256];
__device__ int    g_mbsum[256];
__device__ float  g_cA[H];
__device__ float  g_d1[H];

// pre-split transposed weights: [0,65536)=Wm(K=512); then 6 H x H mats
#define WTOT (65536 + 6 * 16384)
__device__ __nv_bfloat16 g_Wth[WTOT];
__device__ __nv_bfloat16 g_Wtl[WTOT];

// ---------------- split helpers ----------------------------------------------
__device__ __forceinline__ void split_pair(float x0, float x1, uint32_t& hi01, uint32_t& lo01) {
    uint32_t xi = __float_as_uint(x0), yi = __float_as_uint(x1);
    hi01 = __byte_perm(xi, yi, 0x7632);
    float rx = x0 - __uint_as_float(xi & 0xFFFF0000u);
    float ry = x1 - __uint_as_float(yi & 0xFFFF0000u);
    asm("cvt.rn.bf16x2.f32 %0, %1, %2;" : "=r"(lo01) : "f"(ry), "f"(rx));
}
__device__ __forceinline__ void split2(float x, unsigned short& hi, unsigned short& lo) {
    __nv_bfloat16 h = __float2bfloat16(x);
    float hf = __bfloat162float(h);
    __nv_bfloat16 l = __float2bfloat16(x - hf);
    hi = __bfloat16_as_ushort(h);
    lo = __bfloat16_as_ushort(l);
}
__device__ __forceinline__ void mma16816(float* d, const uint32_t* a, uint32_t b0, uint32_t b1) {
    asm volatile("mma.sync.aligned.m16n8k16.row.col.f32.bf16.bf16.f32 "
                 "{%0,%1,%2,%3}, {%4,%5,%6,%7}, {%8,%9}, {%0,%1,%2,%3};\n"
                 : "+f"(d[0]), "+f"(d[1]), "+f"(d[2]), "+f"(d[3])
                 : "r"(a[0]), "r"(a[1]), "r"(a[2]), "r"(a[3]), "r"(b0), "r"(b1));
}

// ---------------- small kernels ----------------------------------------------
__global__ void zero_kernel(float* __restrict__ p, int n4) {
    int i = blockIdx.x * blockDim.x + threadIdx.x;
    if (i < n4) ((float4*)p)[i] = make_float4(0.f, 0.f, 0.f, 0.f);
}
__global__ void prep_weights(const float* __restrict__ Wm,
                             const float* __restrict__ M0, const float* __restrict__ M1,
                             const float* __restrict__ M2, const float* __restrict__ M3,
                             const float* __restrict__ M4, const float* __restrict__ M5) {
    int idx = blockIdx.x * blockDim.x + threadIdx.x;
    if (idx >= WTOT) return;
    const float* src; int K, off;
    if (idx < 65536) { src = Wm; K = 512; off = idx; }
    else {
        int r = idx - 65536;
        int m = r >> 14; off = r & 16383; K = 128;
        src = (m == 0) ? M0 : (m == 1) ? M1 : (m == 2) ? M2 : (m == 3) ? M3 : (m == 4) ? M4 : M5;
    }
    int n = off / K, k = off - n * K;
    float v = src[(size_t)k * H + n];
    unsigned short h, l;
    split2(v, h, l);
    ((unsigned short*)g_Wth)[idx] = h;
    ((unsigned short*)g_Wtl)[idx] = l;
}
__global__ void count_kernel(const int* __restrict__ src, const int* __restrict__ dst, int E) {
    int e = blockIdx.x * blockDim.x + threadIdx.x;
    if (e < E) {
        atomicAdd(&g_ucnt[src[e]], 1);
        atomicAdd(&g_mcnt[dst[e]], 1);
    }
}
__global__ void scan1_kernel(const int* __restrict__ in, int* __restrict__ out,
                             int* __restrict__ bsums, int n) {
    __shared__ int s[1024];
    int i = blockIdx.x * 1024 + threadIdx.x;
    int x = (i < n) ? in[i] : 0;
    s[threadIdx.x] = x;
    __syncthreads();
    #pragma unroll
    for (int d = 1; d < 1024; d <<= 1) {
        int t = (threadIdx.x >= d) ? s[threadIdx.x - d] : 0;
        __syncthreads();
        s[threadIdx.x] += t;
        __syncthreads();
    }
    if (i < n) out[i] = s[threadIdx.x] - x;
    if (threadIdx.x == 1023) bsums[blockIdx.x] = s[1023];
}
__global__ void scan2_kernel(int* __restrict__ bsums, int nb, int* __restrict__ offs, int n) {
    if (threadIdx.x == 0 && blockIdx.x == 0) {
        int run = 0;
        for (int i = 0; i < nb; i++) { int v = bsums[i]; bsums[i] = run; run += v; }
        offs[n] = run;
    }
}
__global__ void scan3_kernel(int* __restrict__ offs, const int* __restrict__ bsums,
                             int* __restrict__ cur, int n) {
    int i = blockIdx.x * blockDim.x + threadIdx.x;
    if (i < n) {
        int v = offs[i] + bsums[i >> 10];
        offs[i] = v;
        cur[i] = v;
    }
}
__global__ void fill_u_kernel(const int* __restrict__ src, const int* __restrict__ dst, int E) {
    int e = blockIdx.x * blockDim.x + threadIdx.x;
    if (e >= E) return;
    int pu = atomicAdd(&g_ucur[src[e]], 1);
    g_uadj[pu] = dst[e];
}
__global__ void fill_m_kernel(const int* __restrict__ src, const int* __restrict__ dst, int E) {
    int e = blockIdx.x * blockDim.x + threadIdx.x;
    if (e >= E) return;
    int pm = atomicAdd(&g_mcur[dst[e]], 1);
    g_madj[pm] = src[e];
}
__global__ void vec_kernel(const float* __restrict__ u0, const float* __restrict__ Wl1um,
                           const float* __restrict__ bl1mu, const float* __restrict__ Wr1mu) {
    int j = threadIdx.x;
    float a = 0.f, b = 0.f;
    for (int k = 0; k < H; k++) {
        float u = u0[k];
        a += u * Wl1um[k * H + j];
        b += u * Wr1mu[k * H + j];
    }
    g_cA[j] = a;
    g_d1[j] = b + bl1mu[j];
}

// warp-per-node CSR gather over fp16 rows: 16 lanes x 16B, 2 rows/iter.
// OUTK: 0=f32, 1=f16, 2=bf16 hi/lo planes. FUSED1: mean+d1+relu. MEAN: mean only.
template<int OUTK, bool FUSED1, bool MEAN>
__global__ void gather_kernel(const __half* __restrict__ rows, const int* __restrict__ adj,
                              const int* __restrict__ offs, void* __restrict__ out,
                              void* __restrict__ outl, const float* __restrict__ d1, int N)
{
    int node = (blockIdx.x * blockDim.x + threadIdx.x) >> 5;
    int lane = threadIdx.x & 31;
    if (node >= N) return;
    int beg = offs[node], end = offs[node + 1];
    int hsel = lane >> 4;
    int sub  = lane & 15;
    float acc[8];
    #pragma unroll
    for (int j = 0; j < 8; j++) acc[j] = 0.f;

    for (int base = beg; base < end; base += 32) {
        int nn = min(32, end - base);
        int myidx = (lane < nn) ? __ldg(&adj[base + lane]) : 0;
        int np = (nn + 1) >> 1;
        #pragma unroll 4
        for (int t = 0; t < np; t++) {
            int sel = 2 * t + hsel;
            int ii = __shfl_sync(0xffffffffu, myidx, sel & 31);
            if (sel < nn) {
                uint4 v = *(const uint4*)&rows[(size_t)ii * H + sub * 8];
                float2 f0 = __half22float2(*(__half2*)&v.x);
                float2 f1 = __half22float2(*(__half2*)&v.y);
                float2 f2 = __half22float2(*(__half2*)&v.z);
                float2 f3 = __half22float2(*(__half2*)&v.w);
                acc[0] += f0.x; acc[1] += f0.y; acc[2] += f1.x; acc[3] += f1.y;
                acc[4] += f2.x; acc[5] += f2.y; acc[6] += f3.x; acc[7] += f3.y;
            }
        }
    }
    #pragma unroll
    for (int j = 0; j < 8; j++) acc[j] += __shfl_xor_sync(0xffffffffu, acc[j], 16);

    if (lane < 16) {
        if (FUSED1) {
            float rinv = 1.f / fmaxf((float)(end - beg), 1.f);
            float4 d0 = *(const float4*)&d1[sub * 8];
            float4 d4 = *(const float4*)&d1[sub * 8 + 4];
            acc[0] = fmaxf(acc[0] * rinv + d0.x, 0.f);
            acc[1] = fmaxf(acc[1] * rinv + d0.y, 0.f);
            acc[2] = fmaxf(acc[2] * rinv + d0.z, 0.f);
            acc[3] = fmaxf(acc[3] * rinv + d0.w, 0.f);
            acc[4] = fmaxf(acc[4] * rinv + d4.x, 0.f);
            acc[5] = fmaxf(acc[5] * rinv + d4.y, 0.f);
            acc[6] = fmaxf(acc[6] * rinv + d4.z, 0.f);
            acc[7] = fmaxf(acc[7] * rinv + d4.w, 0.f);
        } else if (MEAN) {
            float rinv = 1.f / fmaxf((float)(end - beg), 1.f);
            #pragma unroll
            for (int j = 0; j < 8; j++) acc[j] *= rinv;
        }
        size_t off = (size_t)node * H + sub * 8;
        if (OUTK == 1) {
            uint4 pk;
            *(__half2*)&pk.x = __floats2half2_rn(acc[0], acc[1]);
            *(__half2*)&pk.y = __floats2half2_rn(acc[2], acc[3]);
            *(__half2*)&pk.z = __floats2half2_rn(acc[4], acc[5]);
            *(__half2*)&pk.w = __floats2half2_rn(acc[6], acc[7]);
            *(uint4*)&((__half*)out)[off] = pk;
        } else if (OUTK == 2) {
            uint4 ph, pl;
            split_pair(acc[0], acc[1], ph.x, pl.x);
            split_pair(acc[2], acc[3], ph.y, pl.y);
            split_pair(acc[4], acc[5], ph.z, pl.z);
            split_pair(acc[6], acc[7], ph.w, pl.w);
            *(uint4*)&((__nv_bfloat16*)out)[off]  = ph;
            *(uint4*)&((__nv_bfloat16*)outl)[off] = pl;
        } else {
            float* o = &((float*)out)[off];
            *(float4*)o       = make_float4(acc[0], acc[1], acc[2], acc[3]);
            *(float4*)(o + 4) = make_float4(acc[4], acc[5], acc[6], acc[7]);
        }
    }
}

// dot over fp16 tables: 2 edges per warp, 16 lanes x uint4 per edge
__global__ void dot_kernel(const int* __restrict__ lu, const int* __restrict__ lm,
                           const __half* __restrict__ uo, const __half* __restrict__ mo,
                           float* __restrict__ out, int EL) {
    int wpair = (blockIdx.x * blockDim.x + threadIdx.x) >> 5;
    int lane = threadIdx.x & 31;
    int e = wpair * 2 + (lane >> 4);
    int sub = lane & 15;
    float s = 0.f;
    if (e < EL) {
        int u = __ldg(&lu[e]);
        int m = __ldg(&lm[e]);
        uint4 av = *(const uint4*)&uo[(size_t)u * H + sub * 8];
        uint4 bv = *(const uint4*)&mo[(size_t)m * H + sub * 8];
        float2 a0 = __half22float2(*(__half2*)&av.x), b0 = __half22float2(*(__half2*)&bv.x);
        float2 a1 = __half22float2(*(__half2*)&av.y), b1 = __half22float2(*(__half2*)&bv.y);
        float2 a2 = __half22float2(*(__half2*)&av.z), b2 = __half22float2(*(__half2*)&bv.z);
        float2 a3 = __half22float2(*(__half2*)&av.w), b3 = __half22float2(*(__half2*)&bv.w);
        s = a0.x * b0.x + a0.y * b0.y + a1.x * b1.x + a1.y * b1.y
          + a2.x * b2.x + a2.y * b2.y + a3.x * b3.x + a3.y * b3.y;
    }
    #pragma unroll
    for (int o = 8; o; o >>= 1) s += __shfl_xor_sync(0xffffffffu, s, o);
    if (sub == 0 && e < EL) out[e] = s;
}

// ---------------- GEMM common -------------------------------------------------
#define SROW 72
#define SROWF 136
#define GSMEM (4 * 128 * SROW * 2 + 512)
#define GSMEM_D2B (2 * 128 * SROWF * 2 + 2 * 128 * SROW * 2 + 512)

__device__ __forceinline__ void load_B_pre(const __nv_bfloat16* __restrict__ Wth,
                                           const __nv_bfloat16* __restrict__ Wtl,
                                           int K, int kbase,
                                           __nv_bfloat16* sBh, __nv_bfloat16* sBl, int tid) {
    #pragma unroll
    for (int t = 0; t < 4; t++) {
        int idx = tid + t * 256;
        int n = idx >> 3, kq = idx & 7;
        size_t go = (size_t)n * K + kbase + kq * 8;
        uint4 h = *(const uint4*)&Wth[go];
        uint4 l = *(const uint4*)&Wtl[go];
        int o = n * SROW + kq * 8;
        *(uint4*)&sBh[o] = h;
        *(uint4*)&sBl[o] = l;
    }
}
__device__ __forceinline__ void load_A_planes(const __nv_bfloat16* __restrict__ Ah,
                                              const __nv_bfloat16* __restrict__ Al,
                                              int KTOT, int kbase, int row0, int M,
                                              __nv_bfloat16* sAh, __nv_bfloat16* sAl, int tid) {
    #pragma unroll
    for (int t = 0; t < 4; t++) {
        int idx = tid + t * 256;
        int r = idx >> 3, q = idx & 7;
        int rg = row0 + r;
        uint4 h = make_uint4(0, 0, 0, 0), l = make_uint4(0, 0, 0, 0);
        if (rg < M) {
            size_t go = (size_t)rg * KTOT + kbase + q * 8;
            h = *(const uint4*)&Ah[go];
            l = *(const uint4*)&Al[go];
        }
        int o = r * SROW + q * 8;
        *(uint4*)&sAh[o] = h;
        *(uint4*)&sAl[o] = l;
    }
}

template<int AST>
__device__ __forceinline__ void compute_chunk(const __nv_bfloat16* sAh, const __nv_bfloat16* sAl,
                                              const __nv_bfloat16* sBh, const __nv_bfloat16* sBl,
                                              int akof, int wm, int wn, int g, int tig,
                                              float acc[2][8][4]) {
    #pragma unroll
    for (int ks = 0; ks < 4; ks++) {
        int kof = ks * 16 + tig * 2;
        uint32_t ah[2][4], al[2][4];
        #pragma unroll
        for (int i = 0; i < 2; i++) {
            int r0 = (wm * 32 + i * 16 + g) * AST + akof + kof;
            int r1 = r0 + 8 * AST;
            ah[i][0] = *(const uint32_t*)&sAh[r0];
            ah[i][1] = *(const uint32_t*)&sAh[r1];
            ah[i][2] = *(const uint32_t*)&sAh[r0 + 8];
            ah[i][3] = *(const uint32_t*)&sAh[r1 + 8];
            al[i][0] = *(const uint32_t*)&sAl[r0];
            al[i][1] = *(const uint32_t*)&sAl[r1];
            al[i][2] = *(const uint32_t*)&sAl[r0 + 8];
            al[i][3] = *(const uint32_t*)&sAl[r1 + 8];
        }
        #pragma unroll
        for (int j = 0; j < 8; j++) {
            int nb = (wn * 64 + j * 8 + g) * SROW + kof;
            uint32_t bh0 = *(const uint32_t*)&sBh[nb];
            uint32_t bh1 = *(const uint32_t*)&sBh[nb + 8];
            uint32_t bl0 = *(const uint32_t*)&sBl[nb];
            uint32_t bl1 = *(const uint32_t*)&sBl[nb + 8];
            mma16816(acc[0][j], ah[0], bh0, bh1);
            mma16816(acc[1][j], ah[1], bh0, bh1);
            mma16816(acc[0][j], ah[0], bl0, bl1);
            mma16816(acc[1][j], ah[1], bl0, bl1);
            mma16816(acc[0][j], al[0], bh0, bh1);
            mma16816(acc[1][j], al[1], bh0, bh1);
        }
    }
}

// ---------------- generic GEMM ------------------------------------------------
// AK: 0=f32 (cheap split), 1=f16 (cheap split), 2=planes
// CK: 0=f32, 1=f16, 2=planes ; ADDM: 0=none, 1=f32, 2=f16
template<int KTOT, int AK, int CK, bool BIAS, int ADDM>
__global__ void __launch_bounds__(256)
gemm_mma(const void* __restrict__ Av, const void* __restrict__ Avl,
         const __nv_bfloat16* __restrict__ Wth, const __nv_bfloat16* __restrict__ Wtl,
         const float* __restrict__ bias, const void* __restrict__ addmat,
         void* __restrict__ Cv, void* __restrict__ Cvl, int M)
{
    extern __shared__ char smem[];
    __nv_bfloat16* sAh = (__nv_bfloat16*)smem;
    __nv_bfloat16* sAl = sAh + 128 * SROW;
    __nv_bfloat16* sBh = sAl + 128 * SROW;
    __nv_bfloat16* sBl = sBh + 128 * SROW;

    const int tid = threadIdx.x;
    const int wid = tid >> 5, lid = tid & 31;
    const int wm = wid >> 1, wn = wid & 1;
    const int g = lid >> 2, tig = lid & 3;
    const int row0 = blockIdx.x * 128;

    float acc[2][8][4];
    #pragma unroll
    for (int i = 0; i < 2; i++)
        #pragma unroll
        for (int j = 0; j < 8; j++)
            #pragma unroll
            for (int q = 0; q < 4; q++) acc[i][j][q] = 0.f;

    const int NCH = KTOT / 64;
    for (int c = 0; c < NCH; c++) {
        if (c > 0) __syncthreads();
        if (AK == 2) {
            load_A_planes((const __nv_bfloat16*)Av, (const __nv_bfloat16*)Avl,
                          KTOT, c * 64, row0, M, sAh, sAl, tid);
        } else {
            #pragma unroll
            for (int t = 0; t < 8; t++) {
                int idx = tid + t * 256;
                int r = idx >> 4, q = idx & 15;
                int rg = row0 + r;
                float4 v = make_float4(0.f, 0.f, 0.f, 0.f);
                if (rg < M) {
                    if (AK == 1) {
                        const __half* A = (const __half*)Av;
                        uint2 hv = *(const uint2*)&A[(size_t)rg * KTOT + c * 64 + q * 4];
                        float2 f0 = __half22float2(*(__half2*)&hv.x);
                        float2 f1 = __half22float2(*(__half2*)&hv.y);
                        v = make_float4(f0.x, f0.y, f1.x, f1.y);
                    } else {
                        v = *(const float4*)&((const float*)Av)[(size_t)rg * KTOT + c * 64 + q * 4];
                    }
                }
                uint2 hp, lp;
                split_pair(v.x, v.y, hp.x, lp.x);
                split_pair(v.z, v.w, hp.y, lp.y);
                int o = r * SROW + q * 4;
                *(uint2*)&sAh[o] = hp;
                *(uint2*)&sAl[o] = lp;
            }
        }
        load_B_pre(Wth, Wtl, KTOT, c * 64, sBh, sBl, tid);
        __syncthreads();
        compute_chunk<SROW>(sAh, sAl, sBh, sBl, 0, wm, wn, g, tig, acc);
    }

    #pragma unroll
    for (int i = 0; i < 2; i++) {
        #pragma unroll
        for (int hf = 0; hf < 2; hf++) {
            int r = row0 + wm * 32 + i * 16 + g + hf * 8;
            if (r >= M) continue;
            #pragma unroll
            for (int j = 0; j < 8; j++) {
                int col = wn * 64 + j * 8 + tig * 2;
                float x0 = acc[i][j][hf * 2 + 0];
                float x1 = acc[i][j][hf * 2 + 1];
                if (BIAS) { x0 += bias[col]; x1 += bias[col + 1]; }
                size_t off = (size_t)r * H + col;
                if (ADDM == 1) {
                    float2 m = *(const float2*)&((const float*)addmat)[off];
                    x0 += m.x; x1 += m.y;
                } else if (ADDM == 2) {
                    uint32_t mv = *(const uint32_t*)&((const __half*)addmat)[off];
                    float2 m = __half22float2(*(__half2*)&mv);
                    x0 += m.x; x1 += m.y;
                }
                if (CK == 1) {
                    *(__half2*)&((__half*)Cv)[off] = __floats2half2_rn(x0, x1);
                } else if (CK == 2) {
                    uint32_t hh, ll;
                    split_pair(x0, x1, hh, ll);
                    *(uint32_t*)&((__nv_bfloat16*)Cv)[off]  = hh;
                    *(uint32_t*)&((__nv_bfloat16*)Cvl)[off] = ll;
                } else {
                    *(float2*)&((float*)Cv)[off] = make_float2(x0, x1);
                }
            }
        }
    }
}

// ---------------- conv1 movie dual-B (A = movie_x planes) ---------------------
__global__ void __launch_bounds__(256)
gemm_conv1_movie(const __nv_bfloat16* __restrict__ Ah, const __nv_bfloat16* __restrict__ Al,
                 const __nv_bfloat16* __restrict__ W0h, const __nv_bfloat16* __restrict__ W0l,
                 const __nv_bfloat16* __restrict__ W1h, const __nv_bfloat16* __restrict__ W1l,
                 const float* __restrict__ bias1, const float* __restrict__ indvec,
                 const int* __restrict__ cnt,
                 __half* __restrict__ C0, __nv_bfloat16* __restrict__ C1h,
                 __nv_bfloat16* __restrict__ C1l, int M)
{
    extern __shared__ char smem[];
    __nv_bfloat16* sAh = (__nv_bfloat16*)smem;
    __nv_bfloat16* sAl = sAh + 128 * SROWF;
    __nv_bfloat16* sBh = sAl + 128 * SROWF;
    __nv_bfloat16* sBl = sBh + 128 * SROW;

    const int tid = threadIdx.x;
    const int wid = tid >> 5, lid = tid & 31;
    const int wm = wid >> 1, wn = wid & 1;
    const int g = lid >> 2, tig = lid & 3;
    const int row0 = blockIdx.x * 128;

    #pragma unroll
    for (int t = 0; t < 8; t++) {
        int idx = tid + t * 256;
        int r = idx >> 4, q = idx & 15;
        int rg = row0 + r;
        uint4 h = make_uint4(0, 0, 0, 0), l = make_uint4(0, 0, 0, 0);
        if (rg < M) {
            size_t go = (size_t)rg * H + q * 8;
            h = *(const uint4*)&Ah[go];
            l = *(const uint4*)&Al[go];
        }
        int o = r * SROWF + q * 8;
        *(uint4*)&sAh[o] = h;
        *(uint4*)&sAl[o] = l;
    }

    #pragma unroll
    for (int ws = 0; ws < 2; ws++) {
        const __nv_bfloat16* Wh = ws ? W1h : W0h;
        const __nv_bfloat16* Wl = ws ? W1l : W0l;
        float acc[2][8][4];
        #pragma unroll
        for (int i = 0; i < 2; i++)
            #pragma unroll
            for (int j = 0; j < 8; j++)
                #pragma unroll
                for (int q = 0; q < 4; q++) acc[i][j][q] = 0.f;
        #pragma unroll
        for (int c = 0; c < 2; c++) {
            __syncthreads();
            load_B_pre(Wh, Wl, 128, c * 64, sBh, sBl, tid);
            __syncthreads();
            compute_chunk<SROWF>(sAh, sAl, sBh, sBl, c * 64, wm, wn, g, tig, acc);
        }
        #pragma unroll
        for (int i = 0; i < 2; i++) {
            #pragma unroll
            for (int hf = 0; hf < 2; hf++) {
                int r = row0 + wm * 32 + i * 16 + g + hf * 8;
                if (r >= M) continue;
                bool indf = false;
                if (ws) indf = (cnt[r] > 0);
                #pragma unroll
                for (int j = 0; j < 8; j++) {
                    int col = wn * 64 + j * 8 + tig * 2;
                    float x0 = acc[i][j][hf * 2 + 0];
                    float x1 = acc[i][j][hf * 2 + 1];
                    size_t off = (size_t)r * H + col;
                    if (ws) {
                        x0 += bias1[col]; x1 += bias1[col + 1];
                        if (indf) { x0 += indvec[col]; x1 += indvec[col + 1]; }
                        x0 = fmaxf(x0, 0.f); x1 = fmaxf(x1, 0.f);
                        uint32_t hh, ll;
                        split_pair(x0, x1, hh, ll);
                        *(uint32_t*)&C1h[off] = hh;
                        *(uint32_t*)&C1l[off] = ll;
                    } else {
                        *(__half2*)&C0[off] = __floats2half2_rn(x0, x1);
                    }
                }
            }
        }
    }
}

// ---------------- conv2 movie dual-A (planes in, fp16 out, row-ranged) --------
__global__ void __launch_bounds__(256)
gemm_conv2_movie(const __nv_bfloat16* __restrict__ A0h, const __nv_bfloat16* __restrict__ A0l,
                 const __nv_bfloat16* __restrict__ A1h, const __nv_bfloat16* __restrict__ A1l,
                 const __nv_bfloat16* __restrict__ W0h, const __nv_bfloat16* __restrict__ W0l,
                 const __nv_bfloat16* __restrict__ W1h, const __nv_bfloat16* __restrict__ W1l,
                 const float* __restrict__ bias, __half* __restrict__ C,
                 int rowbase, int Mend)
{
    extern __shared__ char smem[];
    __nv_bfloat16* sAh = (__nv_bfloat16*)smem;
    __nv_bfloat16* sAl = sAh + 128 * SROW;
    __nv_bfloat16* sBh = sAl + 128 * SROW;
    __nv_bfloat16* sBl = sBh + 128 * SROW;

    const int tid = threadIdx.x;
    const int wid = tid >> 5, lid = tid & 31;
    const int wm = wid >> 1, wn = wid & 1;
    const int g = lid >> 2, tig = lid & 3;
    const int row0 = rowbase + blockIdx.x * 128;

    float acc[2][8][4];
    #pragma unroll
    for (int i = 0; i < 2; i++)
        #pragma unroll
        for (int j = 0; j < 8; j++)
            #pragma unroll
            for (int q = 0; q < 4; q++) acc[i][j][q] = 0.f;

    #pragma unroll
    for (int c = 0; c < 4; c++) {
        if (c > 0) __syncthreads();
        const __nv_bfloat16* Ah = (c < 2) ? A0h : A1h;
        const __nv_bfloat16* Al = (c < 2) ? A0l : A1l;
        const __nv_bfloat16* Wh = (c < 2) ? W0h : W1h;
        const __nv_bfloat16* Wl = (c < 2) ? W0l : W1l;
        const int ck = (c & 1) * 64;
        load_A_planes(Ah, Al, 128, ck, row0, Mend, sAh, sAl, tid);
        load_B_pre(Wh, Wl, 128, ck, sBh, sBl, tid);
        __syncthreads();
        compute_chunk<SROW>(sAh, sAl, sBh, sBl, 0, wm, wn, g, tig, acc);
    }

    #pragma unroll
    for (int i = 0; i < 2; i++) {
        #pragma unroll
        for (int hf = 0; hf < 2; hf++) {
            int r = row0 + wm * 32 + i * 16 + g + hf * 8;
            if (r >= Mend) continue;
            #pragma unroll
            for (int j = 0; j < 8; j++) {
                int col = wn * 64 + j * 8 + tig * 2;
                float x0 = acc[i][j][hf * 2 + 0] + bias[col];
                float x1 = acc[i][j][hf * 2 + 1] + bias[col + 1];
                *(__half2*)&C[(size_t)r * H + col] = __floats2half2_rn(x0, x1);
            }
        }
    }
}

// ---------------- streams/events: created BEFORE harness checkpoints ----------
static cudaStream_t sCSR = 0, sB = 0;
static cudaEvent_t evFork = 0, evCount = 0, evFillU = 0, evFillM = 0, evC1 = 0,
                   evUH = 0, evUO = 0, evMacc0 = 0, evC2a = 0;
namespace {
struct StreamInit {
    StreamInit() {
        cudaStreamCreateWithFlags(&sCSR, cudaStreamNonBlocking);
        cudaStreamCreateWithFlags(&sB, cudaStreamNonBlocking);
        cudaEventCreateWithFlags(&evFork,  cudaEventDisableTiming);
        cudaEventCreateWithFlags(&evCount, cudaEventDisableTiming);
        cudaEventCreateWithFlags(&evFillU, cudaEventDisableTiming);
        cudaEventCreateWithFlags(&evFillM, cudaEventDisableTiming);
        cudaEventCreateWithFlags(&evC1,    cudaEventDisableTiming);
        cudaEventCreateWithFlags(&evUH,    cudaEventDisableTiming);
        cudaEventCreateWithFlags(&evUO,    cudaEventDisableTiming);
        cudaEventCreateWithFlags(&evMacc0, cudaEventDisableTiming);
        cudaEventCreateWithFlags(&evC2a,   cudaEventDisableTiming);
        zero_kernel<<<1, 32, 0, sCSR>>>(nullptr, 0);
        zero_kernel<<<1, 32, 0, sB>>>(nullptr, 0);
        zero_kernel<<<1, 32>>>(nullptr, 0);
        cudaEventRecord(evFork, 0);
        cudaStreamWaitEvent(sCSR, evFork, 0);
        cudaDeviceSynchronize();
    }
};
static StreamInit s_stream_init;
}

// ---------------- launch ------------------------------------------------------
static inline int cdiv(int a, int b) { return (a + b - 1) / b; }

extern "C" void kernel_launch(void* const* d_in, const int* in_sizes, int n_in,
                              void* d_out, int out_size)
{
    const float* movie_feats = (const float*)d_in[0];
    const float* user_init   = (const float*)d_in[1];
    const int*   edge_src    = (const int*)d_in[2];
    const int*   edge_dst    = (const int*)d_in[3];
    const int*   lbl_user    = (const int*)d_in[4];
    const int*   lbl_movie   = (const int*)d_in[5];
    const float* Wm    = (const float*)d_in[7];
    const float* bm    = (const float*)d_in[8];
    const float* Wl1um = (const float*)d_in[9];
    const float* bl1um = (const float*)d_in[10];
    const float* Wr1um = (const float*)d_in[11];
    const float* Wl1mu = (const float*)d_in[12];
    const float* bl1mu = (const float*)d_in[13];
    const float* Wr1mu = (const float*)d_in[14];
    const float* Wl2um = (const float*)d_in[15];
    const float* bl2um = (const float*)d_in[16];
    const float* Wr2um = (const float*)d_in[17];
    const float* Wl2mu = (const float*)d_in[18];
    const float* bl2mu = (const float*)d_in[19];
    const float* Wr2mu = (const float*)d_in[20];

    const int E  = in_sizes[2];
    const int EL = in_sizes[4];
    const int NM = in_sizes[0] / FDc;
    const int NU = NUc;
    float* out = (float*)d_out;
    (void)n_in; (void)out_size;

    __nv_bfloat16 *p_mxh, *p_mxl, *p_mhh, *p_mhl, *p_mah, *p_mal, *p_Wth, *p_Wtl;
    float *p_cA, *p_d1;
    __half *p_movie_o, *p_movie_y, *p_movie_z, *p_userH, *p_uacc, *p_userO;
    int *p_ucnt, *p_mcnt, *p_uoffs, *p_moffs, *p_ucur, *p_mcur, *p_uadj, *p_madj, *p_ub, *p_mb;
    cudaGetSymbolAddress((void**)&p_mxh, g_mxh);
    cudaGetSymbolAddress((void**)&p_mxl, g_mxl);
    cudaGetSymbolAddress((void**)&p_mhh, g_mhh);
    cudaGetSymbolAddress((void**)&p_mhl, g_mhl);
    cudaGetSymbolAddress((void**)&p_mah, g_mah);
    cudaGetSymbolAddress((void**)&p_mal, g_mal);
    cudaGetSymbolAddress((void**)&p_movie_o, g_movie_o);
    cudaGetSymbolAddress((void**)&p_movie_y, g_movie_y);
    cudaGetSymbolAddress((void**)&p_movie_z, g_movie_z);
    cudaGetSymbolAddress((void**)&p_userH,   g_userH);
    cudaGetSymbolAddress((void**)&p_uacc,    g_uacc);
    cudaGetSymbolAddress((void**)&p_userO,   g_userO);
    cudaGetSymbolAddress((void**)&p_Wth,     g_Wth);
    cudaGetSymbolAddress((void**)&p_Wtl,     g_Wtl);
    cudaGetSymbolAddress((void**)&p_ucnt,    g_ucnt);
    cudaGetSymbolAddress((void**)&p_mcnt,    g_mcnt);
    cudaGetSymbolAddress((void**)&p_uoffs,   g_uoffs);
    cudaGetSymbolAddress((void**)&p_moffs,   g_moffs);
    cudaGetSymbolAddress((void**)&p_ucur,    g_ucur);
    cudaGetSymbolAddress((void**)&p_mcur,    g_mcur);
    cudaGetSymbolAddress((void**)&p_uadj,    g_uadj);
    cudaGetSymbolAddress((void**)&p_madj,    g_madj);
    cudaGetSymbolAddress((void**)&p_ub,      g_ubsum);
    cudaGetSymbolAddress((void**)&p_mb,      g_mbsum);
    cudaGetSymbolAddress((void**)&p_cA,      g_cA);
    cudaGetSymbolAddress((void**)&p_d1,      g_d1);

    const __nv_bfloat16 *Wm_h = p_Wth,             *Wm_l = p_Wtl;
    const __nv_bfloat16 *l1mu_h = p_Wth + 65536,   *l1mu_l = p_Wtl + 65536;
    const __nv_bfloat16 *r1um_h = l1mu_h + 16384,  *r1um_l = l1mu_l + 16384;
    const __nv_bfloat16 *l2um_h = r1um_h + 16384,  *l2um_l = r1um_l + 16384;
    const __nv_bfloat16 *r2um_h = l2um_h + 16384,  *r2um_l = l2um_l + 16384;
    const __nv_bfloat16 *l2mu_h = r2um_h + 16384,  *l2mu_l = r2um_l + 16384;
    const __nv_bfloat16 *r2mu_h = l2mu_h + 16384,  *r2mu_l = l2mu_l + 16384;

    cudaFuncSetAttribute(gemm_mma<FDc, 0, 2, true,  0>, cudaFuncAttributeMaxDynamicSharedMemorySize, GSMEM);
    cudaFuncSetAttribute(gemm_mma<H,   2, 1, false, 0>, cudaFuncAttributeMaxDynamicSharedMemorySize, GSMEM);
    cudaFuncSetAttribute(gemm_mma<H,   1, 1, true,  2>, cudaFuncAttributeMaxDynamicSharedMemorySize, GSMEM);
    cudaFuncSetAttribute(gemm_conv1_movie, cudaFuncAttributeMaxDynamicSharedMemorySize, GSMEM_D2B);
    cudaFuncSetAttribute(gemm_conv2_movie, cudaFuncAttributeMaxDynamicSharedMemorySize, GSMEM);

    const int ZT = 256;

    // ===== main stream: weight prep =====
    prep_weights<<<cdiv(WTOT, 256), 256>>>(Wm, Wl1mu, Wr1um, Wl2um, Wr2um, Wl2mu, Wr2mu);

    // ===== fork CSR build onto sCSR =====
    cudaEventRecord(evFork, 0);
    cudaStreamWaitEvent(sCSR, evFork, 0);
    zero_kernel<<<cdiv(NU / 4, ZT), ZT, 0, sCSR>>>((float*)p_ucnt, NU / 4);
    zero_kernel<<<cdiv(NM / 4, ZT), ZT, 0, sCSR>>>((float*)p_mcnt, NM / 4);
    count_kernel<<<cdiv(E, 256), 256, 0, sCSR>>>(edge_src, edge_dst, E);
    cudaEventRecord(evCount, sCSR);
    int ub = cdiv(NU, 1024), mb = cdiv(NM, 1024);
    scan1_kernel<<<ub, 1024, 0, sCSR>>>(p_ucnt, p_uoffs, p_ub, NU);
    scan2_kernel<<<1, 32, 0, sCSR>>>(p_ub, ub, p_uoffs, NU);
    scan3_kernel<<<cdiv(NU, 256), 256, 0, sCSR>>>(p_uoffs, p_ub, p_ucur, NU);
    fill_u_kernel<<<cdiv(E, 256), 256, 0, sCSR>>>(edge_src, edge_dst, E);
    cudaEventRecord(evFillU, sCSR);
    scan1_kernel<<<mb, 1024, 0, sCSR>>>(p_mcnt, p_moffs, p_mb, NM);
    scan2_kernel<<<1, 32, 0, sCSR>>>(p_mb, mb, p_moffs, NM);
    scan3_kernel<<<cdiv(NM, 256), 256, 0, sCSR>>>(p_moffs, p_mb, p_mcur, NM);
    fill_m_kernel<<<cdiv(E, 256), 256, 0, sCSR>>>(edge_src, edge_dst, E);
    cudaEventRecord(evFillM, sCSR);

    // ===== main stream: movie_x GEMM (overlaps CSR) =====
    gemm_mma<FDc, 0, 2, true, 0><<<cdiv(NM, 128), 256, GSMEM>>>(
        movie_feats, nullptr, Wm_h, Wm_l, bm, nullptr, p_mxh, p_mxl, NM);
    vec_kernel<<<1, H>>>(user_init, Wl1um, bl1mu, Wr1mu);

    // conv1 (A = movie_x planes; writes movie_y f16 + movie_h planes)
    cudaStreamWaitEvent(0, evCount, 0);
    gemm_conv1_movie<<<cdiv(NM, 128), 256, GSMEM_D2B>>>(
        p_mxh, p_mxl, l1mu_h, l1mu_l, r1um_h, r1um_l, bl1um, p_cA, p_mcnt,
        p_movie_y, p_mhh, p_mhl, NM);
    cudaEventRecord(evC1, 0);

    // user_h gather (fp16 out) — waits only on user-side fill
    cudaStreamWaitEvent(0, evFillU, 0);
    gather_kernel<1, true, false><<<cdiv(NU * 32, 256), 256>>>(
        p_movie_y, p_uadj, p_uoffs, p_userH, nullptr, p_d1, NU);
    cudaEventRecord(evUH, 0);

    // ===== chain B on sB: movie_z -> uacc(mean,f16) -> user_o(f16) =====
    cudaStreamWaitEvent(sB, evC1, 0);
    gemm_mma<H, 2, 1, false, 0><<<cdiv(NM, 128), 256, GSMEM, sB>>>(
        p_mhh, p_mhl, l2mu_h, l2mu_l, nullptr, nullptr, p_movie_z, nullptr, NM);
    cudaStreamWaitEvent(sB, evFillU, 0);
    gather_kernel<1, false, true><<<cdiv(NU * 32, 256), 256, 0, sB>>>(
        p_movie_z, p_uadj, p_uoffs, p_uacc, nullptr, nullptr, NU);
    cudaStreamWaitEvent(sB, evUH, 0);
    gemm_mma<H, 1, 1, true, 2><<<cdiv(NU, 128), 256, GSMEM, sB>>>(
        p_userH, nullptr, r2mu_h, r2mu_l, bl2mu, p_uacc, p_userO, nullptr, NU);
    cudaEventRecord(evUO, sB);

    // ===== chain A on main: macc gather + conv2 pipelined in 2 movie chunks ===
    const int NMH = ((NM / 2) + 127) & ~127;   // chunk boundary, multiple of 128
    cudaStreamWaitEvent(0, evFillM, 0);
    // macc chunk 0: movies [0, NMH)
    gather_kernel<2, false, true><<<cdiv(NMH * 32, 256), 256>>>(
        p_userH, p_madj, p_moffs, p_mah, p_mal, nullptr, NMH);
    cudaEventRecord(evMacc0, 0);
    // conv2 chunk 0 on sB (after its chain B work + macc0)
    cudaStreamWaitEvent(sB, evMacc0, 0);
    gemm_conv2_movie<<<cdiv(NMH, 128), 256, GSMEM, sB>>>(
        p_mah, p_mal, p_mhh, p_mhl, l2um_h, l2um_l, r2um_h, r2um_l, bl2um,
        p_movie_o, 0, NMH);
    cudaEventRecord(evC2a, sB);
    // macc chunk 1: movies [NMH, NM)
    gather_kernel<2, false, true><<<cdiv((NM - NMH) * 32, 256), 256>>>(
        p_userH, p_madj, p_moffs + NMH, p_mah + (size_t)NMH * H, p_mal + (size_t)NMH * H,
        nullptr, NM - NMH);
    // conv2 chunk 1 on main
    gemm_conv2_movie<<<cdiv(NM - NMH, 128), 256, GSMEM>>>(
        p_mah, p_mal, p_mhh, p_mhl, l2um_h, l2um_l, r2um_h, r2um_l, bl2um,
        p_movie_o, NMH, NM);

    // ===== join + dot (fp16 feature tables; 2 edges/warp) =====
    cudaStreamWaitEvent(0, evUO, 0);
    cudaStreamWaitEvent(0, evC2a, 0);
    dot_kernel<<<cdiv(EL * 16, 256), 256>>>(lbl_user, lbl_movie, p_userO, p_movie_o, out, EL);
}